// round 10
// baseline (speedup 1.0000x reference)
#include <cuda_runtime.h>
#include <cuda_bf16.h>
#include <cuda_fp16.h>
#include <math.h>
#include <stdint.h>

#define NROWS 32768
#define NBINS 9
#define MAXTILES 272
#define ASTRA 264            /* A smem halves per row (528 B) */
#define BROWB 144            /* B smem row stride bytes (64 halves + pad) */
#define BBUF_SZ 18432        /* 128 * 144 */

/* dynamic smem layout (bytes) */
#define OFF_A    0
#define OFF_B    67584
#define OFF_SPW  104448      /* OFF_B + 2*BBUF_SZ */
#define OFF_PBS  106496
#define OFF_PBS2 108544
#define OFF_SRED 110592
#define SMEM_SZ  112640

__device__ float g_buf0[(size_t)NROWS * 256];
__device__ float g_Wt0[(size_t)256 * 3072];
__device__ float g_Wt1[(size_t)256 * 3072];
__device__ __half g_Wp0[(size_t)NBINS * 256 * 1024];
__device__ __half g_Wp1[(size_t)NBINS * 256 * 1024];
__device__ float g_Pb0[NBINS * 4 * 256];
__device__ float g_Pb1[NBINS * 4 * 256];
__device__ float g_P2[NBINS * 4 * 256];
__device__ float g_Pb2[NBINS * 4];
__device__ int   g_perm[NROWS];
__device__ float g_tp[NROWS];
__device__ int   g_binstart[NBINS + 1];
__device__ int   g_bincnt[NBINS];
__device__ int   g_cur[NBINS];
__device__ int   g_tilebin[MAXTILES];
__device__ int   g_tilem0[MAXTILES];
__device__ int   g_ntiles;

__device__ __forceinline__ void mma_f16(float* c, const uint32_t* a, uint32_t b0, uint32_t b1){
    asm volatile(
        "mma.sync.aligned.m16n8k16.row.col.f32.f16.f16.f32 "
        "{%0,%1,%2,%3},{%4,%5,%6,%7},{%8,%9},{%0,%1,%2,%3};"
        : "+f"(c[0]), "+f"(c[1]), "+f"(c[2]), "+f"(c[3])
        : "r"(a[0]), "r"(a[1]), "r"(a[2]), "r"(a[3]), "r"(b0), "r"(b1));
}
__device__ __forceinline__ uint32_t smem_u32(const void* p){
    uint32_t a;
    asm("{ .reg .u64 t; cvta.to.shared.u64 t, %1; cvt.u32.u64 %0, t; }" : "=r"(a) : "l"(p));
    return a;
}
__device__ __forceinline__ void ldsm4(uint32_t* r, uint32_t a){
    asm volatile("ldmatrix.sync.aligned.m8n8.x4.shared.b16 {%0,%1,%2,%3}, [%4];"
        : "=r"(r[0]), "=r"(r[1]), "=r"(r[2]), "=r"(r[3]) : "r"(a));
}

// ---------------- bin setup ----------------
__global__ void bins_hist(const float* __restrict__ T){
    const int tid = blockIdx.x * blockDim.x + threadIdx.x;
    const int lane = threadIdx.x & 31;
    for (int i = tid; i < NROWS; i += gridDim.x * blockDim.x){
        int b = (int)(T[i] * 9.0f); b = b < 0 ? 0 : (b > 8 ? 8 : b);
        unsigned m = __match_any_sync(__activemask(), b);
        if (lane == __ffs(m) - 1) atomicAdd(&g_bincnt[b], __popc(m));
    }
}
__global__ void bins_scan(){
    if (threadIdx.x == 0){
        int off = 0, nt = 0;
        for (int b = 0; b < NBINS; b++){
            g_binstart[b] = off;
            g_cur[b] = off;
            int cnt = g_bincnt[b];
            for (int ms = 0; ms < cnt; ms += 128){
                g_tilebin[nt] = b; g_tilem0[nt] = off + ms; nt++;
            }
            off += cnt;
        }
        g_binstart[NBINS] = off;
        g_ntiles = nt;
    }
}
__global__ void bins_scatter(const float* __restrict__ T){
    const int tid = blockIdx.x * blockDim.x + threadIdx.x;
    const int lane = threadIdx.x & 31;
    for (int i = tid; i < NROWS; i += gridDim.x * blockDim.x){
        float t = T[i];
        int b = (int)(t * 9.0f); b = b < 0 ? 0 : (b > 8 ? 8 : b);
        unsigned msk = __activemask();
        unsigned m = __match_any_sync(msk, b);
        int ldr = __ffs(m) - 1;
        int pre = __popc(m & ((1u << lane) - 1u));
        int base = 0;
        if (lane == ldr) base = atomicAdd(&g_cur[b], __popc(m));
        base = __shfl_sync(msk, base, ldr);
        g_perm[base + pre] = i;
        g_tp[base + pre] = t;
    }
}

// ---------------- transpose W (3072x256) -> Wt (256x3072), both layers ----------------
__global__ void transpose_w(const float* __restrict__ W0, const float* __restrict__ W1){
    __shared__ float tile[32][33];
    const float* W = blockIdx.z ? W1 : W0;
    float* Wt = blockIdx.z ? g_Wt1 : g_Wt0;
    const int tx = threadIdx.x, ty = threadIdx.y;
    const int k0 = blockIdx.y * 32, o0 = blockIdx.x * 32;
#pragma unroll
    for (int q = 0; q < 4; q++)
        tile[ty + q*8][tx] = W[(size_t)(k0 + ty + q*8) * 256 + o0 + tx];
    __syncthreads();
#pragma unroll
    for (int q = 0; q < 4; q++)
        Wt[(size_t)(o0 + ty + q*8) * 3072 + k0 + tx] = tile[tx][ty + q*8];
}

// ---------------- prep: poly weights/biases + head poly (P2, Pb2) ----------------
__global__ void prep_all(const float* __restrict__ b0, const float* __restrict__ b1,
                         const float* __restrict__ W2, const float* __restrict__ b2){
    const int layer = blockIdx.y;
    const int i = threadIdx.x;
    if (blockIdx.x == 257){
        if (layer) return;
        {   // P2 from W2 (12 x 256)
            const int o = i;
            float w[12];
#pragma unroll
            for (int s = 0; s < 12; s++) w[s] = W2[s*256 + o];
            float p[4] = {w[0], w[1], w[2], w[3]};
            for (int bin = 0; bin < NBINS; bin++){
                if (bin >= 1){
                    float k = (float)bin / 9.0f, ww = w[3 + bin];
                    p[3] += ww; p[2] -= 3.0f*k*ww; p[1] += 3.0f*k*k*ww; p[0] -= k*k*k*ww;
                }
#pragma unroll
                for (int j = 0; j < 4; j++) g_P2[(bin*4 + j)*256 + o] = p[j];
            }
        }
        if (i == 0){  // Pb2 from b2 (12 scalars)
            float w[12];
#pragma unroll
            for (int s = 0; s < 12; s++) w[s] = b2[s];
            float p[4] = {w[0], w[1], w[2], w[3]};
            for (int bin = 0; bin < NBINS; bin++){
                if (bin >= 1){
                    float k = (float)bin / 9.0f, ww = w[3 + bin];
                    p[3] += ww; p[2] -= 3.0f*k*ww; p[1] += 3.0f*k*k*ww; p[0] -= k*k*k*ww;
                }
#pragma unroll
                for (int j = 0; j < 4; j++) g_Pb2[bin*4 + j] = p[j];
            }
        }
        return;
    }
    const float* Wt = layer ? g_Wt1 : g_Wt0;
    const float* Bv = layer ? b1 : b0;
    __half* Hi = layer ? g_Wp1 : g_Wp0;
    float*  Pb = layer ? g_Pb1 : g_Pb0;
    if (blockIdx.x < 256){
        const int o = blockIdx.x;
        float w[12];
#pragma unroll
        for (int s = 0; s < 12; s++) w[s] = Wt[(size_t)o * 3072 + s*256 + i];
        float p[4] = {w[0], w[1], w[2], w[3]};
        for (int bin = 0; bin < NBINS; bin++){
            if (bin >= 1){
                float k = (float)bin / 9.0f, ww = w[3 + bin];
                p[3] += ww; p[2] -= 3.0f*k*ww; p[1] += 3.0f*k*k*ww; p[0] -= k*k*k*ww;
            }
#pragma unroll
            for (int j = 0; j < 4; j++)
                Hi[((size_t)bin*256 + o)*1024 + j*256 + i] = __float2half_rn(p[j]);
        }
    } else {
        const int o = i;
        float w[12];
#pragma unroll
        for (int s = 0; s < 12; s++) w[s] = Bv[s*256 + o];
        float p[4] = {w[0], w[1], w[2], w[3]};
        for (int bin = 0; bin < NBINS; bin++){
            if (bin >= 1){
                float k = (float)bin / 9.0f, ww = w[3 + bin];
                p[3] += ww; p[2] -= 3.0f*k*ww; p[1] += 3.0f*k*k*ww; p[0] -= k*k*k*ww;
            }
#pragma unroll
            for (int j = 0; j < 4; j++) Pb[(bin*4 + j)*256 + o] = p[j];
        }
    }
}

// ---------------- GEMM: Horner-over-accumulator, K=64 slabs; optional fused head ----------------
template<bool GATHER, bool HEAD>
__global__ void __launch_bounds__(256, 2) vc_gemm(
    const float* __restrict__ Xsrc, const __half* __restrict__ WHi,
    const float* __restrict__ Pb, float* __restrict__ Y)
{
    const int tile = blockIdx.x;
    if (tile >= g_ntiles) return;
    extern __shared__ __align__(16) char smem[];
    __half* Ah = (__half*)(smem + OFF_A);
    float* spw  = (float*)(smem + OFF_SPW);
    float* pbs  = (float*)(smem + OFF_PBS);
    float* pbs2 = (float*)(smem + OFF_PBS2);
    float* sred = (float*)(smem + OFF_SRED);

    const int tid = threadIdx.x, wid = tid >> 5, lane = tid & 31;
    const int bin = g_tilebin[tile];
    const int m0  = g_tilem0[tile];
    const int rows = min(128, g_binstart[bin + 1] - m0);
    const int n0 = blockIdx.y * 128;

    if (tid < 128){
        float t = (tid < rows) ? g_tp[m0 + tid] : 0.0f;
        float e = (tid < rows) ? 1.0f : 0.0f;
        spw[tid*4+0] = e; spw[tid*4+1] = e*t; spw[tid*4+2] = e*t*t; spw[tid*4+3] = e*t*t*t;
    }
#pragma unroll
    for (int q = 0; q < 2; q++){
        int idx = q*256 + tid;
        pbs[idx] = Pb[(bin*4 + (idx >> 7))*256 + n0 + (idx & 127)];
        if (HEAD) pbs2[idx] = g_P2[(bin*4 + (idx >> 7))*256 + n0 + (idx & 127)];
    }

    // ---- build A (fp16(x), 128x256) once ----
    const int r = tid >> 1, h = tid & 1;
    const int rs = min(r, rows - 1);
    const float* xrow = Xsrc + (size_t)(GATHER ? g_perm[m0 + rs] : (m0 + rs)) * 256 + h*128;
#pragma unroll
    for (int q8 = 0; q8 < 16; q8++){
        float4 a = *(const float4*)(xrow + q8*8);
        float4 b = *(const float4*)(xrow + q8*8 + 4);
        __half2 h0 = __floats2half2_rn(a.x, a.y), h1 = __floats2half2_rn(a.z, a.w);
        __half2 h2 = __floats2half2_rn(b.x, b.y), h3 = __floats2half2_rn(b.z, b.w);
        *(uint4*)((char*)Ah + r*(ASTRA*2) + h*256 + q8*16) =
            make_uint4(*(uint32_t*)&h0, *(uint32_t*)&h1, *(uint32_t*)&h2, *(uint32_t*)&h3);
    }

    // ---- B prefetch slab 0 (j=3, ic=0) ----
    const size_t wbase = (size_t)bin * 256 * 1024;
    uint4 bh[4];
#pragma unroll
    for (int it = 0; it < 4; it++){
        int idx = it*256 + tid, o = idx >> 3, q = idx & 7;
        bh[it] = *(const uint4*)(WHi + wbase + (size_t)(n0 + o)*1024 + 3*256 + q*8);
    }
#pragma unroll
    for (int it = 0; it < 4; it++){
        int idx = it*256 + tid, o = idx >> 3, q = idx & 7;
        *(uint4*)(smem + OFF_B + o*BROWB + q*16) = bh[it];
    }
    __syncthreads();

    const int wm = (wid >> 1) * 32, wn = (wid & 1) * 64;
    const int lr = lane >> 2, lk = lane & 3;
    const uint32_t aAddrBase = smem_u32(Ah)
        + (uint32_t)(wm + (lane & 15))*(ASTRA*2) + (uint32_t)(lane >> 4)*16;
    const uint32_t bAddrBase = smem_u32(smem + OFF_B)
        + (uint32_t)(wn + (lane >> 4)*8 + (lane & 7))*BROWB + (uint32_t)((lane >> 3) & 1)*16;
    float tA[2][2];
#pragma unroll
    for (int mt = 0; mt < 2; mt++){
        tA[mt][0] = spw[(wm + mt*16 + lr)*4 + 1];
        tA[mt][1] = spw[(wm + mt*16 + lr + 8)*4 + 1];
    }

    float acc[2][8][4];
#pragma unroll
    for (int a = 0; a < 2; a++)
#pragma unroll
        for (int b = 0; b < 8; b++)
#pragma unroll
            for (int c = 0; c < 4; c++) acc[a][b][c] = 0.0f;

    for (int s = 0; s < 16; s++){
        const int buf = s & 1;
        const int ic = s & 3;
        if (s < 15){
            const int sn = s + 1;
            const int koff = (3 - (sn >> 2))*256 + (sn & 3)*64;
#pragma unroll
            for (int it = 0; it < 4; it++){
                int idx = it*256 + tid, o = idx >> 3, q = idx & 7;
                bh[it] = *(const uint4*)(WHi + wbase + (size_t)(n0 + o)*1024 + koff + q*8);
            }
        }
#pragma unroll
        for (int kk = 0; kk < 4; kk++){
            uint32_t af[2][4];
            ldsm4(af[0], aAddrBase + ic*128 + kk*32);
            ldsm4(af[1], aAddrBase + 16*(ASTRA*2) + ic*128 + kk*32);
#pragma unroll
            for (int np = 0; np < 4; np++){
                uint32_t bf[4];
                ldsm4(bf, bAddrBase + buf*BBUF_SZ + np*16*BROWB + kk*32);
#pragma unroll
                for (int mt = 0; mt < 2; mt++){
                    mma_f16(acc[mt][np*2 + 0], af[mt], bf[0], bf[1]);
                    mma_f16(acc[mt][np*2 + 1], af[mt], bf[2], bf[3]);
                }
            }
        }
        if (s < 15){
#pragma unroll
            for (int it = 0; it < 4; it++){
                int idx = it*256 + tid, o = idx >> 3, q = idx & 7;
                *(uint4*)(smem + OFF_B + (buf ^ 1)*BBUF_SZ + o*BROWB + q*16) = bh[it];
            }
        }
        if ((s & 3) == 3 && s < 15){
#pragma unroll
            for (int mt = 0; mt < 2; mt++)
#pragma unroll
                for (int nt = 0; nt < 8; nt++){
                    acc[mt][nt][0] *= tA[mt][0];
                    acc[mt][nt][1] *= tA[mt][0];
                    acc[mt][nt][2] *= tA[mt][1];
                    acc[mt][nt][3] *= tA[mt][1];
                }
        }
        __syncthreads();
    }

    if (!HEAD){
        // epilogue: + poly bias, relu, store
#pragma unroll
        for (int mt = 0; mt < 2; mt++){
#pragma unroll
            for (int half = 0; half < 2; half++){
                int rr = wm + mt*16 + lr + half*8;
                if (rr >= rows) continue;
                float pw0 = spw[rr*4+0], pw1 = spw[rr*4+1], pw2 = spw[rr*4+2], pw3 = spw[rr*4+3];
                float* yp = Y + (size_t)(m0 + rr) * 256 + n0;
#pragma unroll
                for (int nt = 0; nt < 8; nt++){
                    int col = wn + nt*8 + lk*2;
                    float b0 = pw0*pbs[col]   + pw1*pbs[128+col]   + pw2*pbs[256+col]   + pw3*pbs[384+col];
                    float b1 = pw0*pbs[col+1] + pw1*pbs[128+col+1] + pw2*pbs[256+col+1] + pw3*pbs[384+col+1];
                    float v0 = fmaxf(acc[mt][nt][half*2 + 0] + b0, 0.0f);
                    float v1 = fmaxf(acc[mt][nt][half*2 + 1] + b1, 0.0f);
                    *(float2*)(yp + col) = make_float2(v0, v1);
                }
            }
        }
    } else {
        // fused head: out[row] = sum_j pw_j * sum_n relu(y)*P2_j[n]  (+ bias2)
#pragma unroll
        for (int q = 0; q < 2; q++) sred[q*256 + tid] = 0.0f;
        __syncthreads();
#pragma unroll
        for (int mt = 0; mt < 2; mt++){
#pragma unroll
            for (int half = 0; half < 2; half++){
                int rr = wm + mt*16 + lr + half*8;
                float pw0 = spw[rr*4+0], pw1 = spw[rr*4+1], pw2 = spw[rr*4+2], pw3 = spw[rr*4+3];
                float s0 = 0.f, s1 = 0.f, s2 = 0.f, s3 = 0.f;
#pragma unroll
                for (int nt = 0; nt < 8; nt++){
                    int col = wn + nt*8 + lk*2;
                    float b0 = pw0*pbs[col]   + pw1*pbs[128+col]   + pw2*pbs[256+col]   + pw3*pbs[384+col];
                    float b1 = pw0*pbs[col+1] + pw1*pbs[128+col+1] + pw2*pbs[256+col+1] + pw3*pbs[384+col+1];
                    float v0 = fmaxf(acc[mt][nt][half*2 + 0] + b0, 0.0f);
                    float v1 = fmaxf(acc[mt][nt][half*2 + 1] + b1, 0.0f);
                    s0 += v0*pbs2[col]     + v1*pbs2[col+1];
                    s1 += v0*pbs2[128+col] + v1*pbs2[128+col+1];
                    s2 += v0*pbs2[256+col] + v1*pbs2[256+col+1];
                    s3 += v0*pbs2[384+col] + v1*pbs2[384+col+1];
                }
                // reduce over the 4 lanes (lk) sharing this row
#pragma unroll
                for (int off = 1; off <= 2; off <<= 1){
                    s0 += __shfl_xor_sync(0xffffffffu, s0, off);
                    s1 += __shfl_xor_sync(0xffffffffu, s1, off);
                    s2 += __shfl_xor_sync(0xffffffffu, s2, off);
                    s3 += __shfl_xor_sync(0xffffffffu, s3, off);
                }
                if (lk == 0){
                    atomicAdd(&sred[rr*4 + 0], s0);
                    atomicAdd(&sred[rr*4 + 1], s1);
                    atomicAdd(&sred[rr*4 + 2], s2);
                    atomicAdd(&sred[rr*4 + 3], s3);
                }
            }
        }
        __syncthreads();
        if (tid < rows){
            float pw0 = spw[tid*4+0], pw1 = spw[tid*4+1], pw2 = spw[tid*4+2], pw3 = spw[tid*4+3];
            float rsl = pw0*sred[tid*4+0] + pw1*sred[tid*4+1]
                      + pw2*sred[tid*4+2] + pw3*sred[tid*4+3];
            if (n0 == 0)
                rsl += pw0*g_Pb2[bin*4+0] + pw1*g_Pb2[bin*4+1]
                     + pw2*g_Pb2[bin*4+2] + pw3*g_Pb2[bin*4+3];
            atomicAdd(&Y[g_perm[m0 + tid]], rsl);
        }
    }
}

extern "C" void kernel_launch(void* const* d_in, const int* in_sizes, int n_in,
                              void* d_out, int out_size)
{
    const float* T  = (const float*)d_in[0];
    const float* X  = (const float*)d_in[1];
    const float* W0 = (const float*)d_in[2];
    const float* b0 = (const float*)d_in[3];
    const float* W1 = (const float*)d_in[4];
    const float* b1 = (const float*)d_in[5];
    const float* W2 = (const float*)d_in[6];
    const float* b2 = (const float*)d_in[7];
    float* out = (float*)d_out;

    float *buf0, *pb0, *pb1;
    __half *wp0, *wp1;
    int* bincnt;
    cudaGetSymbolAddress((void**)&buf0, g_buf0);
    cudaGetSymbolAddress((void**)&wp0, g_Wp0);
    cudaGetSymbolAddress((void**)&wp1, g_Wp1);
    cudaGetSymbolAddress((void**)&pb0, g_Pb0);
    cudaGetSymbolAddress((void**)&pb1, g_Pb1);
    cudaGetSymbolAddress((void**)&bincnt, g_bincnt);

    cudaFuncSetAttribute(vc_gemm<true,  false>, cudaFuncAttributeMaxDynamicSharedMemorySize, SMEM_SZ);
    cudaFuncSetAttribute(vc_gemm<false, true >, cudaFuncAttributeMaxDynamicSharedMemorySize, SMEM_SZ);

    cudaMemsetAsync(bincnt, 0, NBINS * sizeof(int), 0);
    cudaMemsetAsync(out, 0, NROWS * sizeof(float), 0);
    bins_hist<<<64, 512>>>(T);
    bins_scan<<<1, 32>>>();
    bins_scatter<<<64, 512>>>(T);
    transpose_w<<<dim3(8, 96, 2), dim3(32, 8)>>>(W0, W1);
    prep_all<<<dim3(258, 2), 256>>>(b0, b1, W2, b2);

    dim3 grid(MAXTILES, 2);
    vc_gemm<true,  false><<<grid, 256, SMEM_SZ>>>(X,    wp0, pb0, buf0);
    vc_gemm<false, true ><<<grid, 256, SMEM_SZ>>>(buf0, wp1, pb1, out);
}

// round 11
// speedup vs baseline: 1.0853x; 1.0853x over previous
#include <cuda_runtime.h>
#include <cuda_bf16.h>
#include <cuda_fp16.h>
#include <math.h>
#include <stdint.h>

#define NROWS 32768
#define NBINS 9
#define MAXTILES 272
#define ASTRA 264            /* A smem halves per row (528 B) */
#define BROWB 144            /* B smem row stride bytes */
#define BBUF_SZ 18432        /* 128 * 144 */

/* dynamic smem layout (bytes) */
#define OFF_A    0
#define OFF_B    67584
#define OFF_SPW  104448      /* OFF_B + 2*BBUF_SZ */
#define OFF_PBS  106496
#define OFF_PBS2 108544
#define OFF_SRED 110592
#define SMEM_SZ  112640

__device__ __half g_buf0[(size_t)NROWS * 256];
__device__ float g_Wt0[(size_t)256 * 3072];
__device__ float g_Wt1[(size_t)256 * 3072];
__device__ __half g_Wp0[(size_t)NBINS * 256 * 1024];
__device__ __half g_Wp1[(size_t)NBINS * 256 * 1024];
__device__ float g_Pb0[NBINS * 4 * 256];
__device__ float g_Pb1[NBINS * 4 * 256];
__device__ float g_P2[NBINS * 4 * 256];
__device__ float g_Pb2[NBINS * 4];
__device__ int   g_perm[NROWS];
__device__ float g_tp[NROWS];
__device__ int   g_binstart[NBINS + 1];
__device__ int   g_bincnt[NBINS];
__device__ int   g_cur[NBINS];
__device__ int   g_tilebin[MAXTILES];
__device__ int   g_tilem0[MAXTILES];
__device__ int   g_ntiles;

__device__ __forceinline__ void mma_f16(float* c, const uint32_t* a, uint32_t b0, uint32_t b1){
    asm volatile(
        "mma.sync.aligned.m16n8k16.row.col.f32.f16.f16.f32 "
        "{%0,%1,%2,%3},{%4,%5,%6,%7},{%8,%9},{%0,%1,%2,%3};"
        : "+f"(c[0]), "+f"(c[1]), "+f"(c[2]), "+f"(c[3])
        : "r"(a[0]), "r"(a[1]), "r"(a[2]), "r"(a[3]), "r"(b0), "r"(b1));
}
__device__ __forceinline__ uint32_t smem_u32(const void* p){
    uint32_t a;
    asm("{ .reg .u64 t; cvta.to.shared.u64 t, %1; cvt.u32.u64 %0, t; }" : "=r"(a) : "l"(p));
    return a;
}
__device__ __forceinline__ void ldsm4(uint32_t* r, uint32_t a){
    asm volatile("ldmatrix.sync.aligned.m8n8.x4.shared.b16 {%0,%1,%2,%3}, [%4];"
        : "=r"(r[0]), "=r"(r[1]), "=r"(r[2]), "=r"(r[3]) : "r"(a));
}
__device__ __forceinline__ void cpasync16(uint32_t dst, const void* src){
    asm volatile("cp.async.cg.shared.global [%0], [%1], 16;" :: "r"(dst), "l"(src) : "memory");
}
#define CP_COMMIT() asm volatile("cp.async.commit_group;" ::: "memory")
#define CP_WAIT0()  asm volatile("cp.async.wait_group 0;" ::: "memory")

// ---------------- bin setup ----------------
__global__ void bins_hist(const float* __restrict__ T){
    const int tid = blockIdx.x * blockDim.x + threadIdx.x;
    const int lane = threadIdx.x & 31;
    for (int i = tid; i < NROWS; i += gridDim.x * blockDim.x){
        int b = (int)(T[i] * 9.0f); b = b < 0 ? 0 : (b > 8 ? 8 : b);
        unsigned m = __match_any_sync(__activemask(), b);
        if (lane == __ffs(m) - 1) atomicAdd(&g_bincnt[b], __popc(m));
    }
}
__global__ void bins_scan(){
    if (threadIdx.x == 0){
        int off = 0, nt = 0;
        for (int b = 0; b < NBINS; b++){
            g_binstart[b] = off;
            g_cur[b] = off;
            int cnt = g_bincnt[b];
            for (int ms = 0; ms < cnt; ms += 128){
                g_tilebin[nt] = b; g_tilem0[nt] = off + ms; nt++;
            }
            off += cnt;
        }
        g_binstart[NBINS] = off;
        g_ntiles = nt;
    }
}
__global__ void bins_scatter(const float* __restrict__ T){
    const int tid = blockIdx.x * blockDim.x + threadIdx.x;
    const int lane = threadIdx.x & 31;
    for (int i = tid; i < NROWS; i += gridDim.x * blockDim.x){
        float t = T[i];
        int b = (int)(t * 9.0f); b = b < 0 ? 0 : (b > 8 ? 8 : b);
        unsigned msk = __activemask();
        unsigned m = __match_any_sync(msk, b);
        int ldr = __ffs(m) - 1;
        int pre = __popc(m & ((1u << lane) - 1u));
        int base = 0;
        if (lane == ldr) base = atomicAdd(&g_cur[b], __popc(m));
        base = __shfl_sync(msk, base, ldr);
        g_perm[base + pre] = i;
        g_tp[base + pre] = t;
    }
}

// ---------------- transpose W (3072x256) -> Wt (256x3072), both layers ----------------
__global__ void transpose_w(const float* __restrict__ W0, const float* __restrict__ W1){
    __shared__ float tile[32][33];
    const float* W = blockIdx.z ? W1 : W0;
    float* Wt = blockIdx.z ? g_Wt1 : g_Wt0;
    const int tx = threadIdx.x, ty = threadIdx.y;
    const int k0 = blockIdx.y * 32, o0 = blockIdx.x * 32;
#pragma unroll
    for (int q = 0; q < 4; q++)
        tile[ty + q*8][tx] = W[(size_t)(k0 + ty + q*8) * 256 + o0 + tx];
    __syncthreads();
#pragma unroll
    for (int q = 0; q < 4; q++)
        Wt[(size_t)(o0 + ty + q*8) * 3072 + k0 + tx] = tile[tx][ty + q*8];
}

// ---------------- prep: poly weights/biases + head poly ----------------
__global__ void prep_all(const float* __restrict__ b0, const float* __restrict__ b1,
                         const float* __restrict__ W2, const float* __restrict__ b2){
    const int layer = blockIdx.y;
    const int i = threadIdx.x;
    if (blockIdx.x == 257){
        if (layer) return;
        {
            const int o = i;
            float w[12];
#pragma unroll
            for (int s = 0; s < 12; s++) w[s] = W2[s*256 + o];
            float p[4] = {w[0], w[1], w[2], w[3]};
            for (int bin = 0; bin < NBINS; bin++){
                if (bin >= 1){
                    float k = (float)bin / 9.0f, ww = w[3 + bin];
                    p[3] += ww; p[2] -= 3.0f*k*ww; p[1] += 3.0f*k*k*ww; p[0] -= k*k*k*ww;
                }
#pragma unroll
                for (int j = 0; j < 4; j++) g_P2[(bin*4 + j)*256 + o] = p[j];
            }
        }
        if (i == 0){
            float w[12];
#pragma unroll
            for (int s = 0; s < 12; s++) w[s] = b2[s];
            float p[4] = {w[0], w[1], w[2], w[3]};
            for (int bin = 0; bin < NBINS; bin++){
                if (bin >= 1){
                    float k = (float)bin / 9.0f, ww = w[3 + bin];
                    p[3] += ww; p[2] -= 3.0f*k*ww; p[1] += 3.0f*k*k*ww; p[0] -= k*k*k*ww;
                }
#pragma unroll
                for (int j = 0; j < 4; j++) g_Pb2[bin*4 + j] = p[j];
            }
        }
        return;
    }
    const float* Wt = layer ? g_Wt1 : g_Wt0;
    const float* Bv = layer ? b1 : b0;
    __half* Hi = layer ? g_Wp1 : g_Wp0;
    float*  Pb = layer ? g_Pb1 : g_Pb0;
    if (blockIdx.x < 256){
        const int o = blockIdx.x;
        float w[12];
#pragma unroll
        for (int s = 0; s < 12; s++) w[s] = Wt[(size_t)o * 3072 + s*256 + i];
        float p[4] = {w[0], w[1], w[2], w[3]};
        for (int bin = 0; bin < NBINS; bin++){
            if (bin >= 1){
                float k = (float)bin / 9.0f, ww = w[3 + bin];
                p[3] += ww; p[2] -= 3.0f*k*ww; p[1] += 3.0f*k*k*ww; p[0] -= k*k*k*ww;
            }
#pragma unroll
            for (int j = 0; j < 4; j++)
                Hi[((size_t)bin*256 + o)*1024 + j*256 + i] = __float2half_rn(p[j]);
        }
    } else {
        const int o = i;
        float w[12];
#pragma unroll
        for (int s = 0; s < 12; s++) w[s] = Bv[s*256 + o];
        float p[4] = {w[0], w[1], w[2], w[3]};
        for (int bin = 0; bin < NBINS; bin++){
            if (bin >= 1){
                float k = (float)bin / 9.0f, ww = w[3 + bin];
                p[3] += ww; p[2] -= 3.0f*k*ww; p[1] += 3.0f*k*k*ww; p[0] -= k*k*k*ww;
            }
#pragma unroll
            for (int j = 0; j < 4; j++) Pb[(bin*4 + j)*256 + o] = p[j];
        }
    }
}

// ---------------- GEMM: Horner + cp.async pipeline ----------------
// GATHER=true: layer 1 (A = fp16(X[perm]) via convert; Y = half, relu)
// HEAD=true:   layer 2 (A = buf0 half via cp.async; fused head -> atomicAdd f32 out)
template<bool GATHER, bool HEAD>
__global__ void __launch_bounds__(256, 2) vc_gemm(
    const void* __restrict__ Xsrc, const __half* __restrict__ WHi,
    const float* __restrict__ Pb, void* __restrict__ Y)
{
    const int tile = blockIdx.x;
    if (tile >= g_ntiles) return;
    extern __shared__ __align__(16) char smem[];
    __half* Ah = (__half*)(smem + OFF_A);
    float* spw  = (float*)(smem + OFF_SPW);
    float* pbs  = (float*)(smem + OFF_PBS);
    float* pbs2 = (float*)(smem + OFF_PBS2);
    float* sred = (float*)(smem + OFF_SRED);

    const int tid = threadIdx.x, wid = tid >> 5, lane = tid & 31;
    const int bin = g_tilebin[tile];
    const int m0  = g_tilem0[tile];
    const int rows = min(128, g_binstart[bin + 1] - m0);
    const int n0 = blockIdx.y * 128;

    if (tid < 128){
        float t = (tid < rows) ? g_tp[m0 + tid] : 0.0f;
        float e = (tid < rows) ? 1.0f : 0.0f;
        spw[tid*4+0] = e; spw[tid*4+1] = e*t; spw[tid*4+2] = e*t*t; spw[tid*4+3] = e*t*t*t;
    }
#pragma unroll
    for (int q = 0; q < 2; q++){
        int idx = q*256 + tid;
        pbs[idx] = Pb[(bin*4 + (idx >> 7))*256 + n0 + (idx & 127)];
        if (HEAD) pbs2[idx] = g_P2[(bin*4 + (idx >> 7))*256 + n0 + (idx & 127)];
    }

    // ---- A tile ----
    const int r = tid >> 1, h = tid & 1;
    const int rs = min(r, rows - 1);
    const uint32_t sAbase = smem_u32(Ah);
    if (GATHER){
        const float* xrow = (const float*)Xsrc + (size_t)g_perm[m0 + rs] * 256 + h*128;
#pragma unroll
        for (int q8 = 0; q8 < 16; q8++){
            float4 a = *(const float4*)(xrow + q8*8);
            float4 b = *(const float4*)(xrow + q8*8 + 4);
            __half2 h0 = __floats2half2_rn(a.x, a.y), h1 = __floats2half2_rn(a.z, a.w);
            __half2 h2 = __floats2half2_rn(b.x, b.y), h3 = __floats2half2_rn(b.z, b.w);
            *(uint4*)((char*)Ah + r*(ASTRA*2) + h*256 + q8*16) =
                make_uint4(*(uint32_t*)&h0, *(uint32_t*)&h1, *(uint32_t*)&h2, *(uint32_t*)&h3);
        }
    } else {
        const __half* xrow = (const __half*)Xsrc + (size_t)(m0 + rs) * 256 + h*128;
#pragma unroll
        for (int q8 = 0; q8 < 16; q8++)
            cpasync16(sAbase + (uint32_t)(r*(ASTRA*2) + h*256 + q8*16), xrow + q8*8);
    }

    // ---- B slab 0 cp.async (group 0 = A(if async) + B0) ----
    const size_t wbase = (size_t)bin * 256 * 1024;
    const uint32_t sBbase = smem_u32(smem + OFF_B);
#pragma unroll
    for (int it = 0; it < 4; it++){
        int idx = it*256 + tid, o = idx >> 3, q = idx & 7;
        cpasync16(sBbase + (uint32_t)(o*BROWB + q*16),
                  WHi + wbase + (size_t)(n0 + o)*1024 + 3*256 + q*8);
    }
    CP_COMMIT();
    __syncthreads();   // spw/pbs visible (tA read below)

    const int wm = (wid >> 1) * 32, wn = (wid & 1) * 64;
    const int lr = lane >> 2, lk = lane & 3;
    const uint32_t aAddrBase = sAbase
        + (uint32_t)(wm + (lane & 15))*(ASTRA*2) + (uint32_t)(lane >> 4)*16;
    const uint32_t bAddrBase = sBbase
        + (uint32_t)(wn + (lane >> 4)*8 + (lane & 7))*BROWB + (uint32_t)((lane >> 3) & 1)*16;
    float tA[2][2];
#pragma unroll
    for (int mt = 0; mt < 2; mt++){
        tA[mt][0] = spw[(wm + mt*16 + lr)*4 + 1];
        tA[mt][1] = spw[(wm + mt*16 + lr + 8)*4 + 1];
    }

    float acc[2][8][4];
#pragma unroll
    for (int a = 0; a < 2; a++)
#pragma unroll
        for (int b = 0; b < 8; b++)
#pragma unroll
            for (int c = 0; c < 4; c++) acc[a][b][c] = 0.0f;

    for (int s = 0; s < 16; s++){
        const int buf = s & 1;
        const int ic = s & 3;
        CP_WAIT0();            // slab-s group (and A on s=0) landed
        __syncthreads();       // all threads' data visible; all done reading buf^1
        if (s < 15){
            const int sn = s + 1;
            const int koff = (3 - (sn >> 2))*256 + (sn & 3)*64;
#pragma unroll
            for (int it = 0; it < 4; it++){
                int idx = it*256 + tid, o = idx >> 3, q = idx & 7;
                cpasync16(sBbase + (uint32_t)((buf ^ 1)*BBUF_SZ + o*BROWB + q*16),
                          WHi + wbase + (size_t)(n0 + o)*1024 + koff + q*8);
            }
            CP_COMMIT();
        }
#pragma unroll
        for (int kk = 0; kk < 4; kk++){
            uint32_t af[2][4];
            ldsm4(af[0], aAddrBase + ic*128 + kk*32);
            ldsm4(af[1], aAddrBase + 16*(ASTRA*2) + ic*128 + kk*32);
#pragma unroll
            for (int np = 0; np < 4; np++){
                uint32_t bf[4];
                ldsm4(bf, bAddrBase + buf*BBUF_SZ + np*16*BROWB + kk*32);
#pragma unroll
                for (int mt = 0; mt < 2; mt++){
                    mma_f16(acc[mt][np*2 + 0], af[mt], bf[0], bf[1]);
                    mma_f16(acc[mt][np*2 + 1], af[mt], bf[2], bf[3]);
                }
            }
        }
        if ((s & 3) == 3 && s < 15){
#pragma unroll
            for (int mt = 0; mt < 2; mt++)
#pragma unroll
                for (int nt = 0; nt < 8; nt++){
                    acc[mt][nt][0] *= tA[mt][0];
                    acc[mt][nt][1] *= tA[mt][0];
                    acc[mt][nt][2] *= tA[mt][1];
                    acc[mt][nt][3] *= tA[mt][1];
                }
        }
    }

    if (!HEAD){
        // epilogue: + poly bias, relu, store half
#pragma unroll
        for (int mt = 0; mt < 2; mt++){
#pragma unroll
            for (int half = 0; half < 2; half++){
                int rr = wm + mt*16 + lr + half*8;
                if (rr >= rows) continue;
                float pw0 = spw[rr*4+0], pw1 = spw[rr*4+1], pw2 = spw[rr*4+2], pw3 = spw[rr*4+3];
                __half* yp = (__half*)Y + (size_t)(m0 + rr) * 256 + n0;
#pragma unroll
                for (int nt = 0; nt < 8; nt++){
                    int col = wn + nt*8 + lk*2;
                    float b0 = pw0*pbs[col]   + pw1*pbs[128+col]   + pw2*pbs[256+col]   + pw3*pbs[384+col];
                    float b1 = pw0*pbs[col+1] + pw1*pbs[128+col+1] + pw2*pbs[256+col+1] + pw3*pbs[384+col+1];
                    float v0 = fmaxf(acc[mt][nt][half*2 + 0] + b0, 0.0f);
                    float v1 = fmaxf(acc[mt][nt][half*2 + 1] + b1, 0.0f);
                    *(__half2*)(yp + col) = __floats2half2_rn(v0, v1);
                }
            }
        }
    } else {
        // fused head
#pragma unroll
        for (int q = 0; q < 2; q++) sred[q*256 + tid] = 0.0f;
        __syncthreads();
#pragma unroll
        for (int mt = 0; mt < 2; mt++){
#pragma unroll
            for (int half = 0; half < 2; half++){
                int rr = wm + mt*16 + lr + half*8;
                float pw0 = spw[rr*4+0], pw1 = spw[rr*4+1], pw2 = spw[rr*4+2], pw3 = spw[rr*4+3];
                float s0 = 0.f, s1 = 0.f, s2 = 0.f, s3 = 0.f;
#pragma unroll
                for (int nt = 0; nt < 8; nt++){
                    int col = wn + nt*8 + lk*2;
                    float b0 = pw0*pbs[col]   + pw1*pbs[128+col]   + pw2*pbs[256+col]   + pw3*pbs[384+col];
                    float b1 = pw0*pbs[col+1] + pw1*pbs[128+col+1] + pw2*pbs[256+col+1] + pw3*pbs[384+col+1];
                    float v0 = fmaxf(acc[mt][nt][half*2 + 0] + b0, 0.0f);
                    float v1 = fmaxf(acc[mt][nt][half*2 + 1] + b1, 0.0f);
                    s0 += v0*pbs2[col]     + v1*pbs2[col+1];
                    s1 += v0*pbs2[128+col] + v1*pbs2[128+col+1];
                    s2 += v0*pbs2[256+col] + v1*pbs2[256+col+1];
                    s3 += v0*pbs2[384+col] + v1*pbs2[384+col+1];
                }
#pragma unroll
                for (int off = 1; off <= 2; off <<= 1){
                    s0 += __shfl_xor_sync(0xffffffffu, s0, off);
                    s1 += __shfl_xor_sync(0xffffffffu, s1, off);
                    s2 += __shfl_xor_sync(0xffffffffu, s2, off);
                    s3 += __shfl_xor_sync(0xffffffffu, s3, off);
                }
                if (lk == 0){
                    atomicAdd(&sred[rr*4 + 0], s0);
                    atomicAdd(&sred[rr*4 + 1], s1);
                    atomicAdd(&sred[rr*4 + 2], s2);
                    atomicAdd(&sred[rr*4 + 3], s3);
                }
            }
        }
        __syncthreads();
        if (tid < rows){
            float pw0 = spw[tid*4+0], pw1 = spw[tid*4+1], pw2 = spw[tid*4+2], pw3 = spw[tid*4+3];
            float rsl = pw0*sred[tid*4+0] + pw1*sred[tid*4+1]
                      + pw2*sred[tid*4+2] + pw3*sred[tid*4+3];
            if (n0 == 0)
                rsl += pw0*g_Pb2[bin*4+0] + pw1*g_Pb2[bin*4+1]
                     + pw2*g_Pb2[bin*4+2] + pw3*g_Pb2[bin*4+3];
            atomicAdd((float*)Y + g_perm[m0 + tid], rsl);
        }
    }
}

extern "C" void kernel_launch(void* const* d_in, const int* in_sizes, int n_in,
                              void* d_out, int out_size)
{
    const float* T  = (const float*)d_in[0];
    const float* X  = (const float*)d_in[1];
    const float* W0 = (const float*)d_in[2];
    const float* b0 = (const float*)d_in[3];
    const float* W1 = (const float*)d_in[4];
    const float* b1 = (const float*)d_in[5];
    const float* W2 = (const float*)d_in[6];
    const float* b2 = (const float*)d_in[7];
    float* out = (float*)d_out;

    __half *buf0, *wp0, *wp1;
    float *pb0, *pb1;
    int* bincnt;
    cudaGetSymbolAddress((void**)&buf0, g_buf0);
    cudaGetSymbolAddress((void**)&wp0, g_Wp0);
    cudaGetSymbolAddress((void**)&wp1, g_Wp1);
    cudaGetSymbolAddress((void**)&pb0, g_Pb0);
    cudaGetSymbolAddress((void**)&pb1, g_Pb1);
    cudaGetSymbolAddress((void**)&bincnt, g_bincnt);

    cudaFuncSetAttribute(vc_gemm<true,  false>, cudaFuncAttributeMaxDynamicSharedMemorySize, SMEM_SZ);
    cudaFuncSetAttribute(vc_gemm<false, true >, cudaFuncAttributeMaxDynamicSharedMemorySize, SMEM_SZ);

    cudaMemsetAsync(bincnt, 0, NBINS * sizeof(int), 0);
    cudaMemsetAsync(out, 0, NROWS * sizeof(float), 0);
    bins_hist<<<64, 512>>>(T);
    bins_scan<<<1, 32>>>();
    bins_scatter<<<64, 512>>>(T);
    transpose_w<<<dim3(8, 96, 2), dim3(32, 8)>>>(W0, W1);
    prep_all<<<dim3(258, 2), 256>>>(b0, b1, W2, b2);

    dim3 grid(MAXTILES, 2);
    vc_gemm<true,  false><<<grid, 256, SMEM_SZ>>>(X,    wp0, pb0, buf0);
    vc_gemm<false, true ><<<grid, 256, SMEM_SZ>>>(buf0, wp1, pb1, out);
}

// round 12
// speedup vs baseline: 1.1024x; 1.0157x over previous
#include <cuda_runtime.h>
#include <cuda_bf16.h>
#include <cuda_fp16.h>
#include <math.h>
#include <stdint.h>

#define NROWS 32768
#define NBINS 9
#define MAXTILES 272
#define ASTRA 264            /* A smem halves per row (528 B) */
#define BROWB 144            /* B smem row stride bytes */
#define BBUF_SZ 18432        /* 128 * 144 */

/* dynamic smem layout (bytes) */
#define OFF_A    0
#define OFF_B    67584
#define OFF_SPW  104448      /* OFF_B + 2*BBUF_SZ */
#define OFF_PBS  106496
#define OFF_PBS2 108544
#define OFF_SRED 110592
#define SMEM_SZ  112640

__device__ __half g_buf0[(size_t)NROWS * 256];
__device__ float g_Wt0[(size_t)256 * 3072];
__device__ float g_Wt1[(size_t)256 * 3072];
__device__ __half g_Wp0[(size_t)NBINS * 256 * 1024];
__device__ __half g_Wp1[(size_t)NBINS * 256 * 1024];
__device__ float g_Pb0[NBINS * 4 * 256];
__device__ float g_Pb1[NBINS * 4 * 256];
__device__ float g_P2[NBINS * 4 * 256];
__device__ float g_Pb2[NBINS * 4];
__device__ int   g_perm[NROWS];
__device__ float g_tp[NROWS];
__device__ int   g_binstart[NBINS + 1];
__device__ int   g_bincnt[NBINS];
__device__ int   g_cur[NBINS];
__device__ int   g_tilebin[MAXTILES];
__device__ int   g_tilem0[MAXTILES];
__device__ int   g_ntiles;

__device__ __forceinline__ void mma_f16(float* c, const uint32_t* a, uint32_t b0, uint32_t b1){
    asm volatile(
        "mma.sync.aligned.m16n8k16.row.col.f32.f16.f16.f32 "
        "{%0,%1,%2,%3},{%4,%5,%6,%7},{%8,%9},{%0,%1,%2,%3};"
        : "+f"(c[0]), "+f"(c[1]), "+f"(c[2]), "+f"(c[3])
        : "r"(a[0]), "r"(a[1]), "r"(a[2]), "r"(a[3]), "r"(b0), "r"(b1));
}
__device__ __forceinline__ uint32_t smem_u32(const void* p){
    uint32_t a;
    asm("{ .reg .u64 t; cvta.to.shared.u64 t, %1; cvt.u32.u64 %0, t; }" : "=r"(a) : "l"(p));
    return a;
}
__device__ __forceinline__ void ldsm4(uint32_t* r, uint32_t a){
    asm volatile("ldmatrix.sync.aligned.m8n8.x4.shared.b16 {%0,%1,%2,%3}, [%4];"
        : "=r"(r[0]), "=r"(r[1]), "=r"(r[2]), "=r"(r[3]) : "r"(a));
}
__device__ __forceinline__ void cpasync16(uint32_t dst, const void* src){
    asm volatile("cp.async.cg.shared.global [%0], [%1], 16;" :: "r"(dst), "l"(src) : "memory");
}
#define CP_COMMIT() asm volatile("cp.async.commit_group;" ::: "memory")
#define CP_WAIT0()  asm volatile("cp.async.wait_group 0;" ::: "memory")

// ---------------- K1: bins_hist (blocks 0..63)  ||  transpose W0/W1 (blocks 64..1599) ----------------
__global__ void fused_setup1(const float* __restrict__ T,
                             const float* __restrict__ W0, const float* __restrict__ W1){
    if (blockIdx.x < 64){
        const int tid = blockIdx.x * 256 + threadIdx.x;
        const int lane = threadIdx.x & 31;
        for (int i = tid; i < NROWS; i += 64 * 256){
            int b = (int)(T[i] * 9.0f); b = b < 0 ? 0 : (b > 8 ? 8 : b);
            unsigned m = __match_any_sync(__activemask(), b);
            if (lane == __ffs(m) - 1) atomicAdd(&g_bincnt[b], __popc(m));
        }
        return;
    }
    __shared__ float tile[32][33];
    const int id = blockIdx.x - 64;            // 0..1535
    const int layer = id / 768;
    const int rem = id % 768;
    const int o0 = (rem & 7) * 32, k0 = (rem >> 3) * 32;
    const float* W = layer ? W1 : W0;
    float* Wt = layer ? g_Wt1 : g_Wt0;
    const int tx = threadIdx.x & 31, ty = threadIdx.x >> 5;
#pragma unroll
    for (int q = 0; q < 4; q++)
        tile[ty + q*8][tx] = W[(size_t)(k0 + ty + q*8) * 256 + o0 + tx];
    __syncthreads();
#pragma unroll
    for (int q = 0; q < 4; q++)
        Wt[(size_t)(o0 + ty + q*8) * 3072 + k0 + tx] = tile[tx][ty + q*8];
}

__global__ void bins_scan(){
    if (threadIdx.x == 0){
        int off = 0, nt = 0;
        for (int b = 0; b < NBINS; b++){
            g_binstart[b] = off;
            g_cur[b] = off;
            int cnt = g_bincnt[b];
            for (int ms = 0; ms < cnt; ms += 128){
                g_tilebin[nt] = b; g_tilem0[nt] = off + ms; nt++;
            }
            off += cnt;
        }
        g_binstart[NBINS] = off;
        g_ntiles = nt;
    }
}

// ---------------- K2: bins_scatter (blocks 0..63)  ||  prep both layers + head poly (64..579) ----------------
__global__ void fused_setup2(const float* __restrict__ T,
                             const float* __restrict__ b0, const float* __restrict__ b1,
                             const float* __restrict__ W2, const float* __restrict__ b2){
    if (blockIdx.x < 64){
        const int tid = blockIdx.x * 256 + threadIdx.x;
        const int lane = threadIdx.x & 31;
        for (int i = tid; i < NROWS; i += 64 * 256){
            float t = T[i];
            int b = (int)(t * 9.0f); b = b < 0 ? 0 : (b > 8 ? 8 : b);
            unsigned msk = __activemask();
            unsigned m = __match_any_sync(msk, b);
            int ldr = __ffs(m) - 1;
            int pre = __popc(m & ((1u << lane) - 1u));
            int base = 0;
            if (lane == ldr) base = atomicAdd(&g_cur[b], __popc(m));
            base = __shfl_sync(msk, base, ldr);
            g_perm[base + pre] = i;
            g_tp[base + pre] = t;
        }
        return;
    }
    const int id = blockIdx.x - 64;            // 0..515
    const int layer = id / 258;
    const int bx = id % 258;
    const int i = threadIdx.x;
    if (bx == 257){
        if (layer) return;
        {
            const int o = i;
            float w[12];
#pragma unroll
            for (int s = 0; s < 12; s++) w[s] = W2[s*256 + o];
            float p[4] = {w[0], w[1], w[2], w[3]};
            for (int bin = 0; bin < NBINS; bin++){
                if (bin >= 1){
                    float k = (float)bin / 9.0f, ww = w[3 + bin];
                    p[3] += ww; p[2] -= 3.0f*k*ww; p[1] += 3.0f*k*k*ww; p[0] -= k*k*k*ww;
                }
#pragma unroll
                for (int j = 0; j < 4; j++) g_P2[(bin*4 + j)*256 + o] = p[j];
            }
        }
        if (i == 0){
            float w[12];
#pragma unroll
            for (int s = 0; s < 12; s++) w[s] = b2[s];
            float p[4] = {w[0], w[1], w[2], w[3]};
            for (int bin = 0; bin < NBINS; bin++){
                if (bin >= 1){
                    float k = (float)bin / 9.0f, ww = w[3 + bin];
                    p[3] += ww; p[2] -= 3.0f*k*ww; p[1] += 3.0f*k*k*ww; p[0] -= k*k*k*ww;
                }
#pragma unroll
                for (int j = 0; j < 4; j++) g_Pb2[bin*4 + j] = p[j];
            }
        }
        return;
    }
    const float* Wt = layer ? g_Wt1 : g_Wt0;
    const float* Bv = layer ? b1 : b0;
    __half* Hi = layer ? g_Wp1 : g_Wp0;
    float*  Pb = layer ? g_Pb1 : g_Pb0;
    if (bx < 256){
        const int o = bx;
        float w[12];
#pragma unroll
        for (int s = 0; s < 12; s++) w[s] = Wt[(size_t)o * 3072 + s*256 + i];
        float p[4] = {w[0], w[1], w[2], w[3]};
        for (int bin = 0; bin < NBINS; bin++){
            if (bin >= 1){
                float k = (float)bin / 9.0f, ww = w[3 + bin];
                p[3] += ww; p[2] -= 3.0f*k*ww; p[1] += 3.0f*k*k*ww; p[0] -= k*k*k*ww;
            }
#pragma unroll
            for (int j = 0; j < 4; j++)
                Hi[((size_t)bin*256 + o)*1024 + j*256 + i] = __float2half_rn(p[j]);
        }
    } else {
        const int o = i;
        float w[12];
#pragma unroll
        for (int s = 0; s < 12; s++) w[s] = Bv[s*256 + o];
        float p[4] = {w[0], w[1], w[2], w[3]};
        for (int bin = 0; bin < NBINS; bin++){
            if (bin >= 1){
                float k = (float)bin / 9.0f, ww = w[3 + bin];
                p[3] += ww; p[2] -= 3.0f*k*ww; p[1] += 3.0f*k*k*ww; p[0] -= k*k*k*ww;
            }
#pragma unroll
            for (int j = 0; j < 4; j++) Pb[(bin*4 + j)*256 + o] = p[j];
        }
    }
}

// ---------------- GEMM: Horner + cp.async pipeline (unchanged from R11) ----------------
template<bool GATHER, bool HEAD>
__global__ void __launch_bounds__(256, 2) vc_gemm(
    const void* __restrict__ Xsrc, const __half* __restrict__ WHi,
    const float* __restrict__ Pb, void* __restrict__ Y)
{
    const int tile = blockIdx.x;
    if (tile >= g_ntiles) return;
    extern __shared__ __align__(16) char smem[];
    __half* Ah = (__half*)(smem + OFF_A);
    float* spw  = (float*)(smem + OFF_SPW);
    float* pbs  = (float*)(smem + OFF_PBS);
    float* pbs2 = (float*)(smem + OFF_PBS2);
    float* sred = (float*)(smem + OFF_SRED);

    const int tid = threadIdx.x, wid = tid >> 5, lane = tid & 31;
    const int bin = g_tilebin[tile];
    const int m0  = g_tilem0[tile];
    const int rows = min(128, g_binstart[bin + 1] - m0);
    const int n0 = blockIdx.y * 128;

    if (tid < 128){
        float t = (tid < rows) ? g_tp[m0 + tid] : 0.0f;
        float e = (tid < rows) ? 1.0f : 0.0f;
        spw[tid*4+0] = e; spw[tid*4+1] = e*t; spw[tid*4+2] = e*t*t; spw[tid*4+3] = e*t*t*t;
    }
#pragma unroll
    for (int q = 0; q < 2; q++){
        int idx = q*256 + tid;
        pbs[idx] = Pb[(bin*4 + (idx >> 7))*256 + n0 + (idx & 127)];
        if (HEAD) pbs2[idx] = g_P2[(bin*4 + (idx >> 7))*256 + n0 + (idx & 127)];
    }

    // ---- A tile ----
    const int r = tid >> 1, h = tid & 1;
    const int rs = min(r, rows - 1);
    const uint32_t sAbase = smem_u32(Ah);
    if (GATHER){
        const float* xrow = (const float*)Xsrc + (size_t)g_perm[m0 + rs] * 256 + h*128;
#pragma unroll
        for (int q8 = 0; q8 < 16; q8++){
            float4 a = *(const float4*)(xrow + q8*8);
            float4 b = *(const float4*)(xrow + q8*8 + 4);
            __half2 h0 = __floats2half2_rn(a.x, a.y), h1 = __floats2half2_rn(a.z, a.w);
            __half2 h2 = __floats2half2_rn(b.x, b.y), h3 = __floats2half2_rn(b.z, b.w);
            *(uint4*)((char*)Ah + r*(ASTRA*2) + h*256 + q8*16) =
                make_uint4(*(uint32_t*)&h0, *(uint32_t*)&h1, *(uint32_t*)&h2, *(uint32_t*)&h3);
        }
    } else {
        const __half* xrow = (const __half*)Xsrc + (size_t)(m0 + rs) * 256 + h*128;
#pragma unroll
        for (int q8 = 0; q8 < 16; q8++)
            cpasync16(sAbase + (uint32_t)(r*(ASTRA*2) + h*256 + q8*16), xrow + q8*8);
    }

    // ---- B slab 0 cp.async ----
    const size_t wbase = (size_t)bin * 256 * 1024;
    const uint32_t sBbase = smem_u32(smem + OFF_B);
#pragma unroll
    for (int it = 0; it < 4; it++){
        int idx = it*256 + tid, o = idx >> 3, q = idx & 7;
        cpasync16(sBbase + (uint32_t)(o*BROWB + q*16),
                  WHi + wbase + (size_t)(n0 + o)*1024 + 3*256 + q*8);
    }
    CP_COMMIT();
    __syncthreads();

    const int wm = (wid >> 1) * 32, wn = (wid & 1) * 64;
    const int lr = lane >> 2, lk = lane & 3;
    const uint32_t aAddrBase = sAbase
        + (uint32_t)(wm + (lane & 15))*(ASTRA*2) + (uint32_t)(lane >> 4)*16;
    const uint32_t bAddrBase = sBbase
        + (uint32_t)(wn + (lane >> 4)*8 + (lane & 7))*BROWB + (uint32_t)((lane >> 3) & 1)*16;
    float tA[2][2];
#pragma unroll
    for (int mt = 0; mt < 2; mt++){
        tA[mt][0] = spw[(wm + mt*16 + lr)*4 + 1];
        tA[mt][1] = spw[(wm + mt*16 + lr + 8)*4 + 1];
    }

    float acc[2][8][4];
#pragma unroll
    for (int a = 0; a < 2; a++)
#pragma unroll
        for (int b = 0; b < 8; b++)
#pragma unroll
            for (int c = 0; c < 4; c++) acc[a][b][c] = 0.0f;

    for (int s = 0; s < 16; s++){
        const int buf = s & 1;
        const int ic = s & 3;
        CP_WAIT0();
        __syncthreads();
        if (s < 15){
            const int sn = s + 1;
            const int koff = (3 - (sn >> 2))*256 + (sn & 3)*64;
#pragma unroll
            for (int it = 0; it < 4; it++){
                int idx = it*256 + tid, o = idx >> 3, q = idx & 7;
                cpasync16(sBbase + (uint32_t)((buf ^ 1)*BBUF_SZ + o*BROWB + q*16),
                          WHi + wbase + (size_t)(n0 + o)*1024 + koff + q*8);
            }
            CP_COMMIT();
        }
#pragma unroll
        for (int kk = 0; kk < 4; kk++){
            uint32_t af[2][4];
            ldsm4(af[0], aAddrBase + ic*128 + kk*32);
            ldsm4(af[1], aAddrBase + 16*(ASTRA*2) + ic*128 + kk*32);
#pragma unroll
            for (int np = 0; np < 4; np++){
                uint32_t bf[4];
                ldsm4(bf, bAddrBase + buf*BBUF_SZ + np*16*BROWB + kk*32);
#pragma unroll
                for (int mt = 0; mt < 2; mt++){
                    mma_f16(acc[mt][np*2 + 0], af[mt], bf[0], bf[1]);
                    mma_f16(acc[mt][np*2 + 1], af[mt], bf[2], bf[3]);
                }
            }
        }
        if ((s & 3) == 3 && s < 15){
#pragma unroll
            for (int mt = 0; mt < 2; mt++)
#pragma unroll
                for (int nt = 0; nt < 8; nt++){
                    acc[mt][nt][0] *= tA[mt][0];
                    acc[mt][nt][1] *= tA[mt][0];
                    acc[mt][nt][2] *= tA[mt][1];
                    acc[mt][nt][3] *= tA[mt][1];
                }
        }
    }

    if (!HEAD){
#pragma unroll
        for (int mt = 0; mt < 2; mt++){
#pragma unroll
            for (int half = 0; half < 2; half++){
                int rr = wm + mt*16 + lr + half*8;
                if (rr >= rows) continue;
                float pw0 = spw[rr*4+0], pw1 = spw[rr*4+1], pw2 = spw[rr*4+2], pw3 = spw[rr*4+3];
                __half* yp = (__half*)Y + (size_t)(m0 + rr) * 256 + n0;
#pragma unroll
                for (int nt = 0; nt < 8; nt++){
                    int col = wn + nt*8 + lk*2;
                    float b0 = pw0*pbs[col]   + pw1*pbs[128+col]   + pw2*pbs[256+col]   + pw3*pbs[384+col];
                    float b1 = pw0*pbs[col+1] + pw1*pbs[128+col+1] + pw2*pbs[256+col+1] + pw3*pbs[384+col+1];
                    float v0 = fmaxf(acc[mt][nt][half*2 + 0] + b0, 0.0f);
                    float v1 = fmaxf(acc[mt][nt][half*2 + 1] + b1, 0.0f);
                    *(__half2*)(yp + col) = __floats2half2_rn(v0, v1);
                }
            }
        }
    } else {
#pragma unroll
        for (int q = 0; q < 2; q++) sred[q*256 + tid] = 0.0f;
        __syncthreads();
#pragma unroll
        for (int mt = 0; mt < 2; mt++){
#pragma unroll
            for (int half = 0; half < 2; half++){
                int rr = wm + mt*16 + lr + half*8;
                float pw0 = spw[rr*4+0], pw1 = spw[rr*4+1], pw2 = spw[rr*4+2], pw3 = spw[rr*4+3];
                float s0 = 0.f, s1 = 0.f, s2 = 0.f, s3 = 0.f;
#pragma unroll
                for (int nt = 0; nt < 8; nt++){
                    int col = wn + nt*8 + lk*2;
                    float b0 = pw0*pbs[col]   + pw1*pbs[128+col]   + pw2*pbs[256+col]   + pw3*pbs[384+col];
                    float b1 = pw0*pbs[col+1] + pw1*pbs[128+col+1] + pw2*pbs[256+col+1] + pw3*pbs[384+col+1];
                    float v0 = fmaxf(acc[mt][nt][half*2 + 0] + b0, 0.0f);
                    float v1 = fmaxf(acc[mt][nt][half*2 + 1] + b1, 0.0f);
                    s0 += v0*pbs2[col]     + v1*pbs2[col+1];
                    s1 += v0*pbs2[128+col] + v1*pbs2[128+col+1];
                    s2 += v0*pbs2[256+col] + v1*pbs2[256+col+1];
                    s3 += v0*pbs2[384+col] + v1*pbs2[384+col+1];
                }
#pragma unroll
                for (int off = 1; off <= 2; off <<= 1){
                    s0 += __shfl_xor_sync(0xffffffffu, s0, off);
                    s1 += __shfl_xor_sync(0xffffffffu, s1, off);
                    s2 += __shfl_xor_sync(0xffffffffu, s2, off);
                    s3 += __shfl_xor_sync(0xffffffffu, s3, off);
                }
                if (lk == 0){
                    atomicAdd(&sred[rr*4 + 0], s0);
                    atomicAdd(&sred[rr*4 + 1], s1);
                    atomicAdd(&sred[rr*4 + 2], s2);
                    atomicAdd(&sred[rr*4 + 3], s3);
                }
            }
        }
        __syncthreads();
        if (tid < rows){
            float pw0 = spw[tid*4+0], pw1 = spw[tid*4+1], pw2 = spw[tid*4+2], pw3 = spw[tid*4+3];
            float rsl = pw0*sred[tid*4+0] + pw1*sred[tid*4+1]
                      + pw2*sred[tid*4+2] + pw3*sred[tid*4+3];
            if (n0 == 0)
                rsl += pw0*g_Pb2[bin*4+0] + pw1*g_Pb2[bin*4+1]
                     + pw2*g_Pb2[bin*4+2] + pw3*g_Pb2[bin*4+3];
            atomicAdd((float*)Y + g_perm[m0 + tid], rsl);
        }
    }
}

extern "C" void kernel_launch(void* const* d_in, const int* in_sizes, int n_in,
                              void* d_out, int out_size)
{
    const float* T  = (const float*)d_in[0];
    const float* X  = (const float*)d_in[1];
    const float* W0 = (const float*)d_in[2];
    const float* b0 = (const float*)d_in[3];
    const float* W1 = (const float*)d_in[4];
    const float* b1 = (const float*)d_in[5];
    const float* W2 = (const float*)d_in[6];
    const float* b2 = (const float*)d_in[7];
    float* out = (float*)d_out;

    __half *buf0, *wp0, *wp1;
    float *pb0, *pb1;
    int* bincnt;
    cudaGetSymbolAddress((void**)&buf0, g_buf0);
    cudaGetSymbolAddress((void**)&wp0, g_Wp0);
    cudaGetSymbolAddress((void**)&wp1, g_Wp1);
    cudaGetSymbolAddress((void**)&pb0, g_Pb0);
    cudaGetSymbolAddress((void**)&pb1, g_Pb1);
    cudaGetSymbolAddress((void**)&bincnt, g_bincnt);

    cudaFuncSetAttribute(vc_gemm<true,  false>, cudaFuncAttributeMaxDynamicSharedMemorySize, SMEM_SZ);
    cudaFuncSetAttribute(vc_gemm<false, true >, cudaFuncAttributeMaxDynamicSharedMemorySize, SMEM_SZ);

    cudaMemsetAsync(bincnt, 0, NBINS * sizeof(int), 0);
    cudaMemsetAsync(out, 0, NROWS * sizeof(float), 0);
    fused_setup1<<<1600, 256>>>(T, W0, W1);
    bins_scan<<<1, 32>>>();
    fused_setup2<<<580, 256>>>(T, b0, b1, W2, b2);

    dim3 grid(MAXTILES, 2);
    vc_gemm<true,  false><<<grid, 256, SMEM_SZ>>>(X,    wp0, pb0, buf0);
    vc_gemm<false, true ><<<grid, 256, SMEM_SZ>>>(buf0, wp1, pb1, out);
}

// round 13
// speedup vs baseline: 1.1425x; 1.0364x over previous
#include <cuda_runtime.h>
#include <cuda_bf16.h>
#include <cuda_fp16.h>
#include <math.h>
#include <stdint.h>

#define NROWS 32768
#define NBINS 9
#define MAXTILES 272
#define ASTRA 264            /* A smem halves per row (528 B) */
#define BROWB 144            /* B smem row stride bytes */
#define BBUF_SZ 18432        /* 128 * 144 */

/* dynamic smem layout (bytes) */
#define OFF_A    0
#define OFF_B    67584
#define OFF_SPW  104448      /* OFF_B + 2*BBUF_SZ */
#define OFF_PBS  106496
#define OFF_PBS2 108544
#define OFF_SRED 110592
#define SMEM_SZ  112640

__device__ __half g_buf0[(size_t)NROWS * 256];
__device__ float g_Wt0[(size_t)256 * 3072];
__device__ float g_Wt1[(size_t)256 * 3072];
__device__ __half g_Wp0[(size_t)NBINS * 256 * 1024];
__device__ __half g_Wp1[(size_t)NBINS * 256 * 1024];
__device__ float g_Pb0[NBINS * 4 * 256];
__device__ float g_Pb1[NBINS * 4 * 256];
__device__ float g_P2[NBINS * 4 * 256];
__device__ float g_Pb2[NBINS * 4];
__device__ int   g_perm[NROWS];
__device__ float g_tp[NROWS];
__device__ int   g_binstart[NBINS + 1];
__device__ int   g_bincnt[NBINS];
__device__ int   g_cur[NBINS];
__device__ int   g_tilebin[MAXTILES];
__device__ int   g_tilem0[MAXTILES];
__device__ int   g_ntiles;

__device__ __forceinline__ void mma_f16(float* c, const uint32_t* a, uint32_t b0, uint32_t b1){
    asm volatile(
        "mma.sync.aligned.m16n8k16.row.col.f32.f16.f16.f32 "
        "{%0,%1,%2,%3},{%4,%5,%6,%7},{%8,%9},{%0,%1,%2,%3};"
        : "+f"(c[0]), "+f"(c[1]), "+f"(c[2]), "+f"(c[3])
        : "r"(a[0]), "r"(a[1]), "r"(a[2]), "r"(a[3]), "r"(b0), "r"(b1));
}
__device__ __forceinline__ uint32_t smem_u32(const void* p){
    uint32_t a;
    asm("{ .reg .u64 t; cvta.to.shared.u64 t, %1; cvt.u32.u64 %0, t; }" : "=r"(a) : "l"(p));
    return a;
}
__device__ __forceinline__ void ldsm4(uint32_t* r, uint32_t a){
    asm volatile("ldmatrix.sync.aligned.m8n8.x4.shared.b16 {%0,%1,%2,%3}, [%4];"
        : "=r"(r[0]), "=r"(r[1]), "=r"(r[2]), "=r"(r[3]) : "r"(a));
}
__device__ __forceinline__ void cpasync16(uint32_t dst, const void* src){
    asm volatile("cp.async.cg.shared.global [%0], [%1], 16;" :: "r"(dst), "l"(src) : "memory");
}
#define CP_COMMIT() asm volatile("cp.async.commit_group;" ::: "memory")
#define CP_WAIT0()  asm volatile("cp.async.wait_group 0;" ::: "memory")

// ---------------- K1: bins_hist (blocks 0..63)  ||  transpose W0/W1 (blocks 64..1599) ----------------
__global__ void fused_setup1(const float* __restrict__ T,
                             const float* __restrict__ W0, const float* __restrict__ W1){
    if (blockIdx.x < 64){
        const int tid = blockIdx.x * 256 + threadIdx.x;
        const int lane = threadIdx.x & 31;
        for (int i = tid; i < NROWS; i += 64 * 256){
            int b = (int)(T[i] * 9.0f); b = b < 0 ? 0 : (b > 8 ? 8 : b);
            unsigned m = __match_any_sync(__activemask(), b);
            if (lane == __ffs(m) - 1) atomicAdd(&g_bincnt[b], __popc(m));
        }
        return;
    }
    __shared__ float tile[32][33];
    const int id = blockIdx.x - 64;
    const int layer = id / 768;
    const int rem = id % 768;
    const int o0 = (rem & 7) * 32, k0 = (rem >> 3) * 32;
    const float* W = layer ? W1 : W0;
    float* Wt = layer ? g_Wt1 : g_Wt0;
    const int tx = threadIdx.x & 31, ty = threadIdx.x >> 5;
#pragma unroll
    for (int q = 0; q < 4; q++)
        tile[ty + q*8][tx] = W[(size_t)(k0 + ty + q*8) * 256 + o0 + tx];
    __syncthreads();
#pragma unroll
    for (int q = 0; q < 4; q++)
        Wt[(size_t)(o0 + ty + q*8) * 3072 + k0 + tx] = tile[tx][ty + q*8];
}

__global__ void bins_scan(){
    if (threadIdx.x == 0){
        int off = 0, nt = 0;
        for (int b = 0; b < NBINS; b++){
            g_binstart[b] = off;
            g_cur[b] = off;
            int cnt = g_bincnt[b];
            for (int ms = 0; ms < cnt; ms += 128){
                g_tilebin[nt] = b; g_tilem0[nt] = off + ms; nt++;
            }
            off += cnt;
        }
        g_binstart[NBINS] = off;
        g_ntiles = nt;
    }
}

// ---------------- K2: bins_scatter || prep ----------------
__global__ void fused_setup2(const float* __restrict__ T,
                             const float* __restrict__ b0, const float* __restrict__ b1,
                             const float* __restrict__ W2, const float* __restrict__ b2){
    if (blockIdx.x < 64){
        const int tid = blockIdx.x * 256 + threadIdx.x;
        const int lane = threadIdx.x & 31;
        for (int i = tid; i < NROWS; i += 64 * 256){
            float t = T[i];
            int b = (int)(t * 9.0f); b = b < 0 ? 0 : (b > 8 ? 8 : b);
            unsigned msk = __activemask();
            unsigned m = __match_any_sync(msk, b);
            int ldr = __ffs(m) - 1;
            int pre = __popc(m & ((1u << lane) - 1u));
            int base = 0;
            if (lane == ldr) base = atomicAdd(&g_cur[b], __popc(m));
            base = __shfl_sync(msk, base, ldr);
            g_perm[base + pre] = i;
            g_tp[base + pre] = t;
        }
        return;
    }
    const int id = blockIdx.x - 64;
    const int layer = id / 258;
    const int bx = id % 258;
    const int i = threadIdx.x;
    if (bx == 257){
        if (layer) return;
        {
            const int o = i;
            float w[12];
#pragma unroll
            for (int s = 0; s < 12; s++) w[s] = W2[s*256 + o];
            float p[4] = {w[0], w[1], w[2], w[3]};
            for (int bin = 0; bin < NBINS; bin++){
                if (bin >= 1){
                    float k = (float)bin / 9.0f, ww = w[3 + bin];
                    p[3] += ww; p[2] -= 3.0f*k*ww; p[1] += 3.0f*k*k*ww; p[0] -= k*k*k*ww;
                }
#pragma unroll
                for (int j = 0; j < 4; j++) g_P2[(bin*4 + j)*256 + o] = p[j];
            }
        }
        if (i == 0){
            float w[12];
#pragma unroll
            for (int s = 0; s < 12; s++) w[s] = b2[s];
            float p[4] = {w[0], w[1], w[2], w[3]};
            for (int bin = 0; bin < NBINS; bin++){
                if (bin >= 1){
                    float k = (float)bin / 9.0f, ww = w[3 + bin];
                    p[3] += ww; p[2] -= 3.0f*k*ww; p[1] += 3.0f*k*k*ww; p[0] -= k*k*k*ww;
                }
#pragma unroll
                for (int j = 0; j < 4; j++) g_Pb2[bin*4 + j] = p[j];
            }
        }
        return;
    }
    const float* Wt = layer ? g_Wt1 : g_Wt0;
    const float* Bv = layer ? b1 : b0;
    __half* Hi = layer ? g_Wp1 : g_Wp0;
    float*  Pb = layer ? g_Pb1 : g_Pb0;
    if (bx < 256){
        const int o = bx;
        float w[12];
#pragma unroll
        for (int s = 0; s < 12; s++) w[s] = Wt[(size_t)o * 3072 + s*256 + i];
        float p[4] = {w[0], w[1], w[2], w[3]};
        for (int bin = 0; bin < NBINS; bin++){
            if (bin >= 1){
                float k = (float)bin / 9.0f, ww = w[3 + bin];
                p[3] += ww; p[2] -= 3.0f*k*ww; p[1] += 3.0f*k*k*ww; p[0] -= k*k*k*ww;
            }
#pragma unroll
            for (int j = 0; j < 4; j++)
                Hi[((size_t)bin*256 + o)*1024 + j*256 + i] = __float2half_rn(p[j]);
        }
    } else {
        const int o = i;
        float w[12];
#pragma unroll
        for (int s = 0; s < 12; s++) w[s] = Bv[s*256 + o];
        float p[4] = {w[0], w[1], w[2], w[3]};
        for (int bin = 0; bin < NBINS; bin++){
            if (bin >= 1){
                float k = (float)bin / 9.0f, ww = w[3 + bin];
                p[3] += ww; p[2] -= 3.0f*k*ww; p[1] += 3.0f*k*k*ww; p[0] -= k*k*k*ww;
            }
#pragma unroll
            for (int j = 0; j < 4; j++) Pb[(bin*4 + j)*256 + o] = p[j];
        }
    }
}

// ---------------- GEMM: Horner + cp.async + register-pipelined fragments ----------------
template<bool GATHER, bool HEAD>
__global__ void __launch_bounds__(256, 2) vc_gemm(
    const void* __restrict__ Xsrc, const __half* __restrict__ WHi,
    const float* __restrict__ Pb, void* __restrict__ Y)
{
    const int tile = blockIdx.x;
    if (tile >= g_ntiles) return;
    extern __shared__ __align__(16) char smem[];
    __half* Ah = (__half*)(smem + OFF_A);
    float* spw  = (float*)(smem + OFF_SPW);
    float* pbs  = (float*)(smem + OFF_PBS);
    float* pbs2 = (float*)(smem + OFF_PBS2);
    float* sred = (float*)(smem + OFF_SRED);

    const int tid = threadIdx.x, wid = tid >> 5, lane = tid & 31;
    const int bin = g_tilebin[tile];
    const int m0  = g_tilem0[tile];
    const int rows = min(128, g_binstart[bin + 1] - m0);
    const int n0 = blockIdx.y * 128;

    if (tid < 128){
        float t = (tid < rows) ? g_tp[m0 + tid] : 0.0f;
        float e = (tid < rows) ? 1.0f : 0.0f;
        spw[tid*4+0] = e; spw[tid*4+1] = e*t; spw[tid*4+2] = e*t*t; spw[tid*4+3] = e*t*t*t;
    }
#pragma unroll
    for (int q = 0; q < 2; q++){
        int idx = q*256 + tid;
        pbs[idx] = Pb[(bin*4 + (idx >> 7))*256 + n0 + (idx & 127)];
        if (HEAD) pbs2[idx] = g_P2[(bin*4 + (idx >> 7))*256 + n0 + (idx & 127)];
    }

    // ---- A tile ----
    const int r = tid >> 1, h = tid & 1;
    const int rs = min(r, rows - 1);
    const uint32_t sAbase = smem_u32(Ah);
    if (GATHER){
        const float* xrow = (const float*)Xsrc + (size_t)g_perm[m0 + rs] * 256 + h*128;
#pragma unroll
        for (int q8 = 0; q8 < 16; q8++){
            float4 a = *(const float4*)(xrow + q8*8);
            float4 b = *(const float4*)(xrow + q8*8 + 4);
            __half2 h0 = __floats2half2_rn(a.x, a.y), h1 = __floats2half2_rn(a.z, a.w);
            __half2 h2 = __floats2half2_rn(b.x, b.y), h3 = __floats2half2_rn(b.z, b.w);
            *(uint4*)((char*)Ah + r*(ASTRA*2) + h*256 + q8*16) =
                make_uint4(*(uint32_t*)&h0, *(uint32_t*)&h1, *(uint32_t*)&h2, *(uint32_t*)&h3);
        }
    } else {
        const __half* xrow = (const __half*)Xsrc + (size_t)(m0 + rs) * 256 + h*128;
#pragma unroll
        for (int q8 = 0; q8 < 16; q8++)
            cpasync16(sAbase + (uint32_t)(r*(ASTRA*2) + h*256 + q8*16), xrow + q8*8);
    }

    // ---- B slab 0 cp.async ----
    const size_t wbase = (size_t)bin * 256 * 1024;
    const uint32_t sBbase = smem_u32(smem + OFF_B);
#pragma unroll
    for (int it = 0; it < 4; it++){
        int idx = it*256 + tid, o = idx >> 3, q = idx & 7;
        cpasync16(sBbase + (uint32_t)(o*BROWB + q*16),
                  WHi + wbase + (size_t)(n0 + o)*1024 + 3*256 + q*8);
    }
    CP_COMMIT();
    __syncthreads();

    const int wm = (wid >> 1) * 32, wn = (wid & 1) * 64;
    const int lr = lane >> 2, lk = lane & 3;
    const uint32_t aAddrBase = sAbase
        + (uint32_t)(wm + (lane & 15))*(ASTRA*2) + (uint32_t)(lane >> 4)*16;
    const uint32_t bAddrBase = sBbase
        + (uint32_t)(wn + (lane >> 4)*8 + (lane & 7))*BROWB + (uint32_t)((lane >> 3) & 1)*16;
    float tA[2][2];
#pragma unroll
    for (int mt = 0; mt < 2; mt++){
        tA[mt][0] = spw[(wm + mt*16 + lr)*4 + 1];
        tA[mt][1] = spw[(wm + mt*16 + lr + 8)*4 + 1];
    }

    float acc[2][8][4];
#pragma unroll
    for (int a = 0; a < 2; a++)
#pragma unroll
        for (int b = 0; b < 8; b++)
#pragma unroll
            for (int c = 0; c < 4; c++) acc[a][b][c] = 0.0f;

    for (int s = 0; s < 16; s++){
        const int buf = s & 1;
        const int ic = s & 3;
        CP_WAIT0();
        __syncthreads();
        if (s < 15){
            const int sn = s + 1;
            const int koff = (3 - (sn >> 2))*256 + (sn & 3)*64;
#pragma unroll
            for (int it = 0; it < 4; it++){
                int idx = it*256 + tid, o = idx >> 3, q = idx & 7;
                cpasync16(sBbase + (uint32_t)((buf ^ 1)*BBUF_SZ + o*BROWB + q*16),
                          WHi + wbase + (size_t)(n0 + o)*1024 + koff + q*8);
            }
            CP_COMMIT();
        }
        // ---- batched A-fragment loads (8 ldsm4 back-to-back, MLP=8) ----
        uint32_t af[4][8];
#pragma unroll
        for (int kk = 0; kk < 4; kk++){
            ldsm4(&af[kk][0], aAddrBase + ic*128 + kk*32);
            ldsm4(&af[kk][4], aAddrBase + 16*(ASTRA*2) + ic*128 + kk*32);
        }
        // ---- B fragments register-double-buffered, one ahead of MMA ----
        const uint32_t bSlab = bAddrBase + buf*BBUF_SZ;
        uint32_t bf[2][4];
        ldsm4(bf[0], bSlab);     // (kk=0, np=0)
#pragma unroll
        for (int kk = 0; kk < 4; kk++){
#pragma unroll
            for (int np = 0; np < 4; np++){
                const int idx = kk*4 + np;
                const int cur = idx & 1;
                if (idx < 15){
                    const int nidx = idx + 1;
                    ldsm4(bf[cur ^ 1], bSlab + (nidx & 3)*16*BROWB + (nidx >> 2)*32);
                }
                mma_f16(acc[0][np*2 + 0], &af[kk][0], bf[cur][0], bf[cur][1]);
                mma_f16(acc[0][np*2 + 1], &af[kk][0], bf[cur][2], bf[cur][3]);
                mma_f16(acc[1][np*2 + 0], &af[kk][4], bf[cur][0], bf[cur][1]);
                mma_f16(acc[1][np*2 + 1], &af[kk][4], bf[cur][2], bf[cur][3]);
            }
        }
        if ((s & 3) == 3 && s < 15){
#pragma unroll
            for (int mt = 0; mt < 2; mt++)
#pragma unroll
                for (int nt = 0; nt < 8; nt++){
                    acc[mt][nt][0] *= tA[mt][0];
                    acc[mt][nt][1] *= tA[mt][0];
                    acc[mt][nt][2] *= tA[mt][1];
                    acc[mt][nt][3] *= tA[mt][1];
                }
        }
    }

    if (!HEAD){
#pragma unroll
        for (int mt = 0; mt < 2; mt++){
#pragma unroll
            for (int half = 0; half < 2; half++){
                int rr = wm + mt*16 + lr + half*8;
                if (rr >= rows) continue;
                float pw0 = spw[rr*4+0], pw1 = spw[rr*4+1], pw2 = spw[rr*4+2], pw3 = spw[rr*4+3];
                __half* yp = (__half*)Y + (size_t)(m0 + rr) * 256 + n0;
#pragma unroll
                for (int nt = 0; nt < 8; nt++){
                    int col = wn + nt*8 + lk*2;
                    float b0 = pw0*pbs[col]   + pw1*pbs[128+col]   + pw2*pbs[256+col]   + pw3*pbs[384+col];
                    float b1 = pw0*pbs[col+1] + pw1*pbs[128+col+1] + pw2*pbs[256+col+1] + pw3*pbs[384+col+1];
                    float v0 = fmaxf(acc[mt][nt][half*2 + 0] + b0, 0.0f);
                    float v1 = fmaxf(acc[mt][nt][half*2 + 1] + b1, 0.0f);
                    *(__half2*)(yp + col) = __floats2half2_rn(v0, v1);
                }
            }
        }
    } else {
#pragma unroll
        for (int q = 0; q < 2; q++) sred[q*256 + tid] = 0.0f;
        __syncthreads();
#pragma unroll
        for (int mt = 0; mt < 2; mt++){
#pragma unroll
            for (int half = 0; half < 2; half++){
                int rr = wm + mt*16 + lr + half*8;
                float pw0 = spw[rr*4+0], pw1 = spw[rr*4+1], pw2 = spw[rr*4+2], pw3 = spw[rr*4+3];
                float s0 = 0.f, s1 = 0.f, s2 = 0.f, s3 = 0.f;
#pragma unroll
                for (int nt = 0; nt < 8; nt++){
                    int col = wn + nt*8 + lk*2;
                    float b0 = pw0*pbs[col]   + pw1*pbs[128+col]   + pw2*pbs[256+col]   + pw3*pbs[384+col];
                    float b1 = pw0*pbs[col+1] + pw1*pbs[128+col+1] + pw2*pbs[256+col+1] + pw3*pbs[384+col+1];
                    float v0 = fmaxf(acc[mt][nt][half*2 + 0] + b0, 0.0f);
                    float v1 = fmaxf(acc[mt][nt][half*2 + 1] + b1, 0.0f);
                    s0 += v0*pbs2[col]     + v1*pbs2[col+1];
                    s1 += v0*pbs2[128+col] + v1*pbs2[128+col+1];
                    s2 += v0*pbs2[256+col] + v1*pbs2[256+col+1];
                    s3 += v0*pbs2[384+col] + v1*pbs2[384+col+1];
                }
#pragma unroll
                for (int off = 1; off <= 2; off <<= 1){
                    s0 += __shfl_xor_sync(0xffffffffu, s0, off);
                    s1 += __shfl_xor_sync(0xffffffffu, s1, off);
                    s2 += __shfl_xor_sync(0xffffffffu, s2, off);
                    s3 += __shfl_xor_sync(0xffffffffu, s3, off);
                }
                if (lk == 0){
                    atomicAdd(&sred[rr*4 + 0], s0);
                    atomicAdd(&sred[rr*4 + 1], s1);
                    atomicAdd(&sred[rr*4 + 2], s2);
                    atomicAdd(&sred[rr*4 + 3], s3);
                }
            }
        }
        __syncthreads();
        if (tid < rows){
            float pw0 = spw[tid*4+0], pw1 = spw[tid*4+1], pw2 = spw[tid*4+2], pw3 = spw[tid*4+3];
            float rsl = pw0*sred[tid*4+0] + pw1*sred[tid*4+1]
                      + pw2*sred[tid*4+2] + pw3*sred[tid*4+3];
            if (n0 == 0)
                rsl += pw0*g_Pb2[bin*4+0] + pw1*g_Pb2[bin*4+1]
                     + pw2*g_Pb2[bin*4+2] + pw3*g_Pb2[bin*4+3];
            atomicAdd((float*)Y + g_perm[m0 + tid], rsl);
        }
    }
}

extern "C" void kernel_launch(void* const* d_in, const int* in_sizes, int n_in,
                              void* d_out, int out_size)
{
    const float* T  = (const float*)d_in[0];
    const float* X  = (const float*)d_in[1];
    const float* W0 = (const float*)d_in[2];
    const float* b0 = (const float*)d_in[3];
    const float* W1 = (const float*)d_in[4];
    const float* b1 = (const float*)d_in[5];
    const float* W2 = (const float*)d_in[6];
    const float* b2 = (const float*)d_in[7];
    float* out = (float*)d_out;

    __half *buf0, *wp0, *wp1;
    float *pb0, *pb1;
    int* bincnt;
    cudaGetSymbolAddress((void**)&buf0, g_buf0);
    cudaGetSymbolAddress((void**)&wp0, g_Wp0);
    cudaGetSymbolAddress((void**)&wp1, g_Wp1);
    cudaGetSymbolAddress((void**)&pb0, g_Pb0);
    cudaGetSymbolAddress((void**)&pb1, g_Pb1);
    cudaGetSymbolAddress((void**)&bincnt, g_bincnt);

    cudaFuncSetAttribute(vc_gemm<true,  false>, cudaFuncAttributeMaxDynamicSharedMemorySize, SMEM_SZ);
    cudaFuncSetAttribute(vc_gemm<false, true >, cudaFuncAttributeMaxDynamicSharedMemorySize, SMEM_SZ);

    cudaMemsetAsync(bincnt, 0, NBINS * sizeof(int), 0);
    cudaMemsetAsync(out, 0, NROWS * sizeof(float), 0);
    fused_setup1<<<1600, 256>>>(T, W0, W1);
    bins_scan<<<1, 32>>>();
    fused_setup2<<<580, 256>>>(T, b0, b1, W2, b2);

    dim3 grid(MAXTILES, 2);
    vc_gemm<true,  false><<<grid, 256, SMEM_SZ>>>(X,    wp0, pb0, buf0);
    vc_gemm<false, true ><<<grid, 256, SMEM_SZ>>>(buf0, wp1, pb1, out);
}

// round 14
// speedup vs baseline: 1.2812x; 1.1215x over previous
#include <cuda_runtime.h>
#include <cuda_bf16.h>
#include <cuda_fp16.h>
#include <math.h>
#include <stdint.h>

#define NROWS 32768
#define NBINS 9
#define MAXTILES 272
#define GEMM1_BLOCKS 544
#define ASTRA 264            /* A smem halves per row (528 B) */
#define BROWB 144            /* B smem row stride bytes */
#define BBUF_SZ 18432        /* 128 * 144 */

/* dynamic smem layout (bytes) */
#define OFF_A    0
#define OFF_B    67584
#define OFF_SPW  104448
#define OFF_PBS  106496
#define OFF_PBS2 108544
#define OFF_SRED 110592
#define SMEM_SZ  112640

__device__ __half g_buf0[(size_t)NROWS * 256];
__device__ float g_Wt0[(size_t)256 * 3072];
__device__ float g_Wt1[(size_t)256 * 3072];
__device__ __half g_Wp0[(size_t)NBINS * 256 * 1024];
__device__ __half g_Wp1[(size_t)NBINS * 256 * 1024];
__device__ float g_Pb0[NBINS * 4 * 256];
__device__ float g_Pb1[NBINS * 4 * 256];
__device__ float g_P2[NBINS * 4 * 256];
__device__ float g_Pb2[NBINS * 4];
__device__ int   g_perm[NROWS];
__device__ float g_tp[NROWS];
__device__ int   g_binstart[NBINS + 1];
__device__ int   g_bincnt[NBINS];
__device__ int   g_cur[NBINS];
__device__ int   g_tilebin[MAXTILES];
__device__ int   g_tilem0[MAXTILES];
__device__ int   g_ntiles;
__device__ int   g_done[MAXTILES];

__device__ __forceinline__ void mma_f16(float* c, const uint32_t* a, uint32_t b0, uint32_t b1){
    asm volatile(
        "mma.sync.aligned.m16n8k16.row.col.f32.f16.f16.f32 "
        "{%0,%1,%2,%3},{%4,%5,%6,%7},{%8,%9},{%0,%1,%2,%3};"
        : "+f"(c[0]), "+f"(c[1]), "+f"(c[2]), "+f"(c[3])
        : "r"(a[0]), "r"(a[1]), "r"(a[2]), "r"(a[3]), "r"(b0), "r"(b1));
}
__device__ __forceinline__ uint32_t smem_u32(const void* p){
    uint32_t a;
    asm("{ .reg .u64 t; cvta.to.shared.u64 t, %1; cvt.u32.u64 %0, t; }" : "=r"(a) : "l"(p));
    return a;
}
__device__ __forceinline__ void ldsm4(uint32_t* r, uint32_t a){
    asm volatile("ldmatrix.sync.aligned.m8n8.x4.shared.b16 {%0,%1,%2,%3}, [%4];"
        : "=r"(r[0]), "=r"(r[1]), "=r"(r[2]), "=r"(r[3]) : "r"(a));
}
__device__ __forceinline__ void cpasync16(uint32_t dst, const void* src){
    asm volatile("cp.async.cg.shared.global [%0], [%1], 16;" :: "r"(dst), "l"(src) : "memory");
}
#define CP_COMMIT() asm volatile("cp.async.commit_group;" ::: "memory")
#define CP_WAIT0()  asm volatile("cp.async.wait_group 0;" ::: "memory")

// ---------------- K1: bins_hist || transpose ----------------
__global__ void fused_setup1(const float* __restrict__ T,
                             const float* __restrict__ W0, const float* __restrict__ W1){
    if (blockIdx.x < 64){
        const int tid = blockIdx.x * 256 + threadIdx.x;
        const int lane = threadIdx.x & 31;
        for (int i = tid; i < NROWS; i += 64 * 256){
            int b = (int)(T[i] * 9.0f); b = b < 0 ? 0 : (b > 8 ? 8 : b);
            unsigned m = __match_any_sync(__activemask(), b);
            if (lane == __ffs(m) - 1) atomicAdd(&g_bincnt[b], __popc(m));
        }
        return;
    }
    __shared__ float tile[32][33];
    const int id = blockIdx.x - 64;
    const int layer = id / 768;
    const int rem = id % 768;
    const int o0 = (rem & 7) * 32, k0 = (rem >> 3) * 32;
    const float* W = layer ? W1 : W0;
    float* Wt = layer ? g_Wt1 : g_Wt0;
    const int tx = threadIdx.x & 31, ty = threadIdx.x >> 5;
#pragma unroll
    for (int q = 0; q < 4; q++)
        tile[ty + q*8][tx] = W[(size_t)(k0 + ty + q*8) * 256 + o0 + tx];
    __syncthreads();
#pragma unroll
    for (int q = 0; q < 4; q++)
        Wt[(size_t)(o0 + ty + q*8) * 3072 + k0 + tx] = tile[tx][ty + q*8];
}

__global__ void bins_scan(){
    if (threadIdx.x == 0){
        int off = 0, nt = 0;
        for (int b = 0; b < NBINS; b++){
            g_binstart[b] = off;
            g_cur[b] = off;
            int cnt = g_bincnt[b];
            for (int ms = 0; ms < cnt; ms += 128){
                g_tilebin[nt] = b; g_tilem0[nt] = off + ms; nt++;
            }
            off += cnt;
        }
        g_binstart[NBINS] = off;
        g_ntiles = nt;
    }
}

// ---------------- K2: bins_scatter || prep ----------------
__global__ void fused_setup2(const float* __restrict__ T,
                             const float* __restrict__ b0, const float* __restrict__ b1,
                             const float* __restrict__ W2, const float* __restrict__ b2){
    if (blockIdx.x < 64){
        const int tid = blockIdx.x * 256 + threadIdx.x;
        const int lane = threadIdx.x & 31;
        for (int i = tid; i < NROWS; i += 64 * 256){
            float t = T[i];
            int b = (int)(t * 9.0f); b = b < 0 ? 0 : (b > 8 ? 8 : b);
            unsigned msk = __activemask();
            unsigned m = __match_any_sync(msk, b);
            int ldr = __ffs(m) - 1;
            int pre = __popc(m & ((1u << lane) - 1u));
            int base = 0;
            if (lane == ldr) base = atomicAdd(&g_cur[b], __popc(m));
            base = __shfl_sync(msk, base, ldr);
            g_perm[base + pre] = i;
            g_tp[base + pre] = t;
        }
        return;
    }
    const int id = blockIdx.x - 64;
    const int layer = id / 258;
    const int bx = id % 258;
    const int i = threadIdx.x;
    if (bx == 257){
        if (layer) return;
        {
            const int o = i;
            float w[12];
#pragma unroll
            for (int s = 0; s < 12; s++) w[s] = W2[s*256 + o];
            float p[4] = {w[0], w[1], w[2], w[3]};
            for (int bin = 0; bin < NBINS; bin++){
                if (bin >= 1){
                    float k = (float)bin / 9.0f, ww = w[3 + bin];
                    p[3] += ww; p[2] -= 3.0f*k*ww; p[1] += 3.0f*k*k*ww; p[0] -= k*k*k*ww;
                }
#pragma unroll
                for (int j = 0; j < 4; j++) g_P2[(bin*4 + j)*256 + o] = p[j];
            }
        }
        if (i == 0){
            float w[12];
#pragma unroll
            for (int s = 0; s < 12; s++) w[s] = b2[s];
            float p[4] = {w[0], w[1], w[2], w[3]};
            for (int bin = 0; bin < NBINS; bin++){
                if (bin >= 1){
                    float k = (float)bin / 9.0f, ww = w[3 + bin];
                    p[3] += ww; p[2] -= 3.0f*k*ww; p[1] += 3.0f*k*k*ww; p[0] -= k*k*k*ww;
                }
#pragma unroll
                for (int j = 0; j < 4; j++) g_Pb2[bin*4 + j] = p[j];
            }
        }
        return;
    }
    const float* Wt = layer ? g_Wt1 : g_Wt0;
    const float* Bv = layer ? b1 : b0;
    __half* Hi = layer ? g_Wp1 : g_Wp0;
    float*  Pb = layer ? g_Pb1 : g_Pb0;
    if (bx < 256){
        const int o = bx;
        float w[12];
#pragma unroll
        for (int s = 0; s < 12; s++) w[s] = Wt[(size_t)o * 3072 + s*256 + i];
        float p[4] = {w[0], w[1], w[2], w[3]};
        for (int bin = 0; bin < NBINS; bin++){
            if (bin >= 1){
                float k = (float)bin / 9.0f, ww = w[3 + bin];
                p[3] += ww; p[2] -= 3.0f*k*ww; p[1] += 3.0f*k*k*ww; p[0] -= k*k*k*ww;
            }
#pragma unroll
            for (int j = 0; j < 4; j++)
                Hi[((size_t)bin*256 + o)*1024 + j*256 + i] = __float2half_rn(p[j]);
        }
    } else {
        const int o = i;
        float w[12];
#pragma unroll
        for (int s = 0; s < 12; s++) w[s] = Bv[s*256 + o];
        float p[4] = {w[0], w[1], w[2], w[3]};
        for (int bin = 0; bin < NBINS; bin++){
            if (bin >= 1){
                float k = (float)bin / 9.0f, ww = w[3 + bin];
                p[3] += ww; p[2] -= 3.0f*k*ww; p[1] += 3.0f*k*k*ww; p[0] -= k*k*k*ww;
            }
#pragma unroll
            for (int j = 0; j < 4; j++) Pb[(bin*4 + j)*256 + o] = p[j];
        }
    }
}

// ---------------- fused dual-layer GEMM ----------------
// blocks [0, 544): layer 1 (A = fp16(X[perm]); Y = g_buf0 half, relu; bump g_done[tile])
// blocks [544, 1088): layer 2 (spin g_done[tile]==2; A = buf0 via cp.async; fused head)
__global__ void __launch_bounds__(256, 2) vc_fused(
    const float* __restrict__ X, float* __restrict__ Out)
{
    const int layer = (blockIdx.x >= GEMM1_BLOCKS) ? 1 : 0;
    const int bb = blockIdx.x - layer * GEMM1_BLOCKS;
    const int tile = bb >> 1;
    if (tile >= g_ntiles) return;
    const int n0 = (bb & 1) * 128;

    extern __shared__ __align__(16) char smem[];
    __half* Ah = (__half*)(smem + OFF_A);
    float* spw  = (float*)(smem + OFF_SPW);
    float* pbs  = (float*)(smem + OFF_PBS);
    float* pbs2 = (float*)(smem + OFF_PBS2);
    float* sred = (float*)(smem + OFF_SRED);

    const int tid = threadIdx.x, wid = tid >> 5, lane = tid & 31;
    const int bin = g_tilebin[tile];
    const int m0  = g_tilem0[tile];
    const int rows = min(128, g_binstart[bin + 1] - m0);

    const __half* WHi = (layer ? g_Wp1 : g_Wp0);
    const float*  Pb  = (layer ? g_Pb1 : g_Pb0);

    if (tid < 128){
        float t = (tid < rows) ? g_tp[m0 + tid] : 0.0f;
        float e = (tid < rows) ? 1.0f : 0.0f;
        spw[tid*4+0] = e; spw[tid*4+1] = e*t; spw[tid*4+2] = e*t*t; spw[tid*4+3] = e*t*t*t;
    }
#pragma unroll
    for (int q = 0; q < 2; q++){
        int idx = q*256 + tid;
        pbs[idx] = Pb[(bin*4 + (idx >> 7))*256 + n0 + (idx & 127)];
        if (layer) pbs2[idx] = g_P2[(bin*4 + (idx >> 7))*256 + n0 + (idx & 127)];
    }

    // ---- B slab 0 cp.async (independent of buf0) ----
    const size_t wbase = (size_t)bin * 256 * 1024;
    const uint32_t sBbase = smem_u32(smem + OFF_B);
#pragma unroll
    for (int it = 0; it < 4; it++){
        int idx = it*256 + tid, o = idx >> 3, q = idx & 7;
        cpasync16(sBbase + (uint32_t)(o*BROWB + q*16),
                  WHi + wbase + (size_t)(n0 + o)*1024 + 3*256 + q*8);
    }
    CP_COMMIT();

    // ---- A tile ----
    const int r = tid >> 1, h = tid & 1;
    const int rs = min(r, rows - 1);
    const uint32_t sAbase = smem_u32(Ah);
    if (!layer){
        const float* xrow = X + (size_t)g_perm[m0 + rs] * 256 + h*128;
#pragma unroll
        for (int q8 = 0; q8 < 16; q8++){
            float4 a = *(const float4*)(xrow + q8*8);
            float4 b = *(const float4*)(xrow + q8*8 + 4);
            __half2 h0 = __floats2half2_rn(a.x, a.y), h1 = __floats2half2_rn(a.z, a.w);
            __half2 h2 = __floats2half2_rn(b.x, b.y), h3 = __floats2half2_rn(b.z, b.w);
            *(uint4*)((char*)Ah + r*(ASTRA*2) + h*256 + q8*16) =
                make_uint4(*(uint32_t*)&h0, *(uint32_t*)&h1, *(uint32_t*)&h2, *(uint32_t*)&h3);
        }
    } else {
        // wait for both layer-1 halves of this tile, then async-copy A
        if (tid == 0){
            while (atomicAdd(&g_done[tile], 0) < 2) {}
        }
        __syncthreads();
        const __half* xrow = g_buf0 + (size_t)(m0 + rs) * 256 + h*128;
#pragma unroll
        for (int q8 = 0; q8 < 16; q8++)
            cpasync16(sAbase + (uint32_t)(r*(ASTRA*2) + h*256 + q8*16), xrow + q8*8);
        CP_COMMIT();
    }
    __syncthreads();

    const int wm = (wid >> 1) * 32, wn = (wid & 1) * 64;
    const int lr = lane >> 2, lk = lane & 3;
    const uint32_t aAddrBase = sAbase
        + (uint32_t)(wm + (lane & 15))*(ASTRA*2) + (uint32_t)(lane >> 4)*16;
    const uint32_t bAddrBase = sBbase
        + (uint32_t)(wn + (lane >> 4)*8 + (lane & 7))*BROWB + (uint32_t)((lane >> 3) & 1)*16;
    float tA[2][2];
#pragma unroll
    for (int mt = 0; mt < 2; mt++){
        tA[mt][0] = spw[(wm + mt*16 + lr)*4 + 1];
        tA[mt][1] = spw[(wm + mt*16 + lr + 8)*4 + 1];
    }

    float acc[2][8][4];
#pragma unroll
    for (int a = 0; a < 2; a++)
#pragma unroll
        for (int b = 0; b < 8; b++)
#pragma unroll
            for (int c = 0; c < 4; c++) acc[a][b][c] = 0.0f;

    for (int s = 0; s < 16; s++){
        const int buf = s & 1;
        const int ic = s & 3;
        CP_WAIT0();
        __syncthreads();
        if (s < 15){
            const int sn = s + 1;
            const int koff = (3 - (sn >> 2))*256 + (sn & 3)*64;
#pragma unroll
            for (int it = 0; it < 4; it++){
                int idx = it*256 + tid, o = idx >> 3, q = idx & 7;
                cpasync16(sBbase + (uint32_t)((buf ^ 1)*BBUF_SZ + o*BROWB + q*16),
                          WHi + wbase + (size_t)(n0 + o)*1024 + koff + q*8);
            }
            CP_COMMIT();
        }
        // ---- fragment ring: af 2-kk lookahead, bf 1-frag lookahead ----
        uint32_t af[2][8], bf[2][4];
        ldsm4(&af[0][0], aAddrBase + ic*128);
        ldsm4(&af[0][4], aAddrBase + 16*(ASTRA*2) + ic*128);
        ldsm4(&af[1][0], aAddrBase + ic*128 + 32);
        ldsm4(&af[1][4], aAddrBase + 16*(ASTRA*2) + ic*128 + 32);
        const uint32_t bSlab = bAddrBase + buf*BBUF_SZ;
        ldsm4(bf[0], bSlab);
#pragma unroll
        for (int idx = 0; idx < 16; idx++){
            const int kk = idx >> 2, np = idx & 3, cur = idx & 1;
            if (idx < 15){
                const int nidx = idx + 1;
                ldsm4(bf[cur ^ 1], bSlab + (nidx & 3)*16*BROWB + (nidx >> 2)*32);
            }
            if (np == 0 && kk >= 1 && kk < 3){
                ldsm4(&af[(kk + 1) & 1][0], aAddrBase + ic*128 + (kk+1)*32);
                ldsm4(&af[(kk + 1) & 1][4], aAddrBase + 16*(ASTRA*2) + ic*128 + (kk+1)*32);
            }
            const uint32_t* a0 = af[kk & 1];
            mma_f16(acc[0][np*2 + 0], a0,     bf[cur][0], bf[cur][1]);
            mma_f16(acc[0][np*2 + 1], a0,     bf[cur][2], bf[cur][3]);
            mma_f16(acc[1][np*2 + 0], a0 + 4, bf[cur][0], bf[cur][1]);
            mma_f16(acc[1][np*2 + 1], a0 + 4, bf[cur][2], bf[cur][3]);
        }
        if ((s & 3) == 3 && s < 15){
#pragma unroll
            for (int mt = 0; mt < 2; mt++)
#pragma unroll
                for (int nt = 0; nt < 8; nt++){
                    acc[mt][nt][0] *= tA[mt][0];
                    acc[mt][nt][1] *= tA[mt][0];
                    acc[mt][nt][2] *= tA[mt][1];
                    acc[mt][nt][3] *= tA[mt][1];
                }
        }
    }

    if (!layer){
#pragma unroll
        for (int mt = 0; mt < 2; mt++){
#pragma unroll
            for (int half = 0; half < 2; half++){
                int rr = wm + mt*16 + lr + half*8;
                if (rr >= rows) continue;
                float pw0 = spw[rr*4+0], pw1 = spw[rr*4+1], pw2 = spw[rr*4+2], pw3 = spw[rr*4+3];
                __half* yp = g_buf0 + (size_t)(m0 + rr) * 256 + n0;
#pragma unroll
                for (int nt = 0; nt < 8; nt++){
                    int col = wn + nt*8 + lk*2;
                    float b0 = pw0*pbs[col]   + pw1*pbs[128+col]   + pw2*pbs[256+col]   + pw3*pbs[384+col];
                    float b1 = pw0*pbs[col+1] + pw1*pbs[128+col+1] + pw2*pbs[256+col+1] + pw3*pbs[384+col+1];
                    float v0 = fmaxf(acc[mt][nt][half*2 + 0] + b0, 0.0f);
                    float v1 = fmaxf(acc[mt][nt][half*2 + 1] + b1, 0.0f);
                    *(__half2*)(yp + col) = __floats2half2_rn(v0, v1);
                }
            }
        }
        __threadfence();
        __syncthreads();
        if (tid == 0) atomicAdd(&g_done[tile], 1);
    } else {
#pragma unroll
        for (int q = 0; q < 2; q++) sred[q*256 + tid] = 0.0f;
        __syncthreads();
#pragma unroll
        for (int mt = 0; mt < 2; mt++){
#pragma unroll
            for (int half = 0; half < 2; half++){
                int rr = wm + mt*16 + lr + half*8;
                float pw0 = spw[rr*4+0], pw1 = spw[rr*4+1], pw2 = spw[rr*4+2], pw3 = spw[rr*4+3];
                float s0 = 0.f, s1 = 0.f, s2 = 0.f, s3 = 0.f;
#pragma unroll
                for (int nt = 0; nt < 8; nt++){
                    int col = wn + nt*8 + lk*2;
                    float b0 = pw0*pbs[col]   + pw1*pbs[128+col]   + pw2*pbs[256+col]   + pw3*pbs[384+col];
                    float b1 = pw0*pbs[col+1] + pw1*pbs[128+col+1] + pw2*pbs[256+col+1] + pw3*pbs[384+col+1];
                    float v0 = fmaxf(acc[mt][nt][half*2 + 0] + b0, 0.0f);
                    float v1 = fmaxf(acc[mt][nt][half*2 + 1] + b1, 0.0f);
                    s0 += v0*pbs2[col]     + v1*pbs2[col+1];
                    s1 += v0*pbs2[128+col] + v1*pbs2[128+col+1];
                    s2 += v0*pbs2[256+col] + v1*pbs2[256+col+1];
                    s3 += v0*pbs2[384+col] + v1*pbs2[384+col+1];
                }
#pragma unroll
                for (int off = 1; off <= 2; off <<= 1){
                    s0 += __shfl_xor_sync(0xffffffffu, s0, off);
                    s1 += __shfl_xor_sync(0xffffffffu, s1, off);
                    s2 += __shfl_xor_sync(0xffffffffu, s2, off);
                    s3 += __shfl_xor_sync(0xffffffffu, s3, off);
                }
                if (lk == 0){
                    atomicAdd(&sred[rr*4 + 0], s0);
                    atomicAdd(&sred[rr*4 + 1], s1);
                    atomicAdd(&sred[rr*4 + 2], s2);
                    atomicAdd(&sred[rr*4 + 3], s3);
                }
            }
        }
        __syncthreads();
        if (tid < rows){
            float pw0 = spw[tid*4+0], pw1 = spw[tid*4+1], pw2 = spw[tid*4+2], pw3 = spw[tid*4+3];
            float rsl = pw0*sred[tid*4+0] + pw1*sred[tid*4+1]
                      + pw2*sred[tid*4+2] + pw3*sred[tid*4+3];
            if (n0 == 0)
                rsl += pw0*g_Pb2[bin*4+0] + pw1*g_Pb2[bin*4+1]
                     + pw2*g_Pb2[bin*4+2] + pw3*g_Pb2[bin*4+3];
            atomicAdd(Out + g_perm[m0 + tid], rsl);
        }
    }
}

extern "C" void kernel_launch(void* const* d_in, const int* in_sizes, int n_in,
                              void* d_out, int out_size)
{
    const float* T  = (const float*)d_in[0];
    const float* X  = (const float*)d_in[1];
    const float* W0 = (const float*)d_in[2];
    const float* b0 = (const float*)d_in[3];
    const float* W1 = (const float*)d_in[4];
    const float* b1 = (const float*)d_in[5];
    const float* W2 = (const float*)d_in[6];
    const float* b2 = (const float*)d_in[7];
    float* out = (float*)d_out;

    int *bincnt, *done;
    cudaGetSymbolAddress((void**)&bincnt, g_bincnt);
    cudaGetSymbolAddress((void**)&done, g_done);

    cudaFuncSetAttribute(vc_fused, cudaFuncAttributeMaxDynamicSharedMemorySize, SMEM_SZ);

    cudaMemsetAsync(bincnt, 0, NBINS * sizeof(int), 0);
    cudaMemsetAsync(done, 0, MAXTILES * sizeof(int), 0);
    cudaMemsetAsync(out, 0, NROWS * sizeof(float), 0);
    fused_setup1<<<1600, 256>>>(T, W0, W1);
    bins_scan<<<1, 32>>>();
    fused_setup2<<<580, 256>>>(T, b0, b1, W2, b2);

    vc_fused<<<2 * GEMM1_BLOCKS, 256, SMEM_SZ>>>(X, out);
}